// round 1
// baseline (speedup 1.0000x reference)
#include <cuda_runtime.h>

namespace {

constexpr int B = 2, N = 4096, D = 256, R = 64;
constexpr int TM = 64, TN = 64;
constexpr int QP = 68;              // padded row stride (floats) for q/k/e tiles: 16B-aligned, conflict-breaking
constexpr int SMEM_FLOATS = 3 * TM * QP + TN * D + TN + TM;
constexpr int SMEM_BYTES  = SMEM_FLOATS * 4;

__device__ float g_q[B * N * R];
__device__ float g_k[B * N * R];

// ---------------------------------------------------------------------------
// Kernel 1: q = val @ Wq, k = val @ Wk   (rows of [B*N, D] x [D, R])
// One block per row; threads 0..63 -> q, 64..127 -> k.
// ---------------------------------------------------------------------------
__global__ void __launch_bounds__(128) qk_kernel(const float* __restrict__ val,
                                                 const float* __restrict__ Wq,
                                                 const float* __restrict__ Wk) {
    __shared__ float v_sm[D];
    const int row = blockIdx.x;          // 0 .. B*N-1
    const int t = threadIdx.x;

    const float2* vrow = reinterpret_cast<const float2*>(val + (size_t)row * D);
    reinterpret_cast<float2*>(v_sm)[t] = vrow[t];
    __syncthreads();

    const float* W = (t < R) ? Wq : Wk;
    const int r = t & (R - 1);
    float acc = 0.f;
#pragma unroll 16
    for (int d = 0; d < D; ++d)
        acc = fmaf(v_sm[d], W[d * R + r], acc);

    float* dst = (t < R) ? g_q : g_k;
    dst[(size_t)row * R + r] = acc;
}

// ---------------------------------------------------------------------------
// Kernel 2: fused scores -> softsign -> (edges@state, edges@val)
// Block = (b, row-tile of TM). Sweeps m in TN tiles. edges never hit HBM.
// ---------------------------------------------------------------------------
__global__ void __launch_bounds__(256) prop_kernel(const float* __restrict__ state,
                                                   const float* __restrict__ val,
                                                   float* __restrict__ out_ds,
                                                   float* __restrict__ out_dv) {
    extern __shared__ float sm[];
    float* q_sm  = sm;                         // TM x QP
    float* k_sm  = q_sm + TM * QP;             // TN x QP
    float* e_sm  = k_sm + TN * QP;             // TM x QP
    float* v_sm  = e_sm + TM * QP;             // TN x D (unpadded)
    float* st_sm = v_sm + TN * D;              // TN
    float* ds_sm = st_sm + TN;                 // TM

    const int b  = blockIdx.y;
    const int n0 = blockIdx.x * TM;
    const int t  = threadIdx.x;

    // Load this block's q tile (padded).
    {
        const float4* src = reinterpret_cast<const float4*>(g_q + ((size_t)b * N + n0) * R);
#pragma unroll
        for (int it = 0; it < (TM * R / 4) / 256; ++it) {
            int p = t + it * 256;              // float4 index
            int i = p / (R / 4), c = p % (R / 4);
            *reinterpret_cast<float4*>(&q_sm[i * QP + c * 4]) = src[p];
        }
    }
    if (t < TM) ds_sm[t] = 0.f;

    // Epilogue-GEMM thread mapping: 16x16 grid, 4 rows x (4 x float4) cols each.
    const int ty = t >> 4, tx = t & 15;
    // Score-phase mapping: 4x4 micro-tile.
    const int ti = t & 15, tj = t >> 4;

    float4 acc[4][4];
#pragma unroll
    for (int a = 0; a < 4; ++a)
#pragma unroll
        for (int c = 0; c < 4; ++c) acc[a][c] = make_float4(0.f, 0.f, 0.f, 0.f);

    for (int m0 = 0; m0 < N; m0 += TN) {
        __syncthreads();   // previous iteration's readers of k/v/e are done; q/ds ready on iter 0

        // Load k tile (padded), v tile, state slice.
        {
            const float4* src = reinterpret_cast<const float4*>(g_k + ((size_t)b * N + m0) * R);
#pragma unroll
            for (int it = 0; it < (TN * R / 4) / 256; ++it) {
                int p = t + it * 256;
                int i = p / (R / 4), c = p % (R / 4);
                *reinterpret_cast<float4*>(&k_sm[i * QP + c * 4]) = src[p];
            }
        }
        {
            const float4* src = reinterpret_cast<const float4*>(val + ((size_t)b * N + m0) * D);
            float4* dst = reinterpret_cast<float4*>(v_sm);
#pragma unroll
            for (int it = 0; it < (TN * D / 4) / 256; ++it)
                dst[t + it * 256] = src[t + it * 256];
        }
        if (t < TN) st_sm[t] = state[b * N + m0 + t];
        __syncthreads();

        // --- Score phase: S[4ti..4ti+3][4tj..4tj+3] over R=64 ---
        float s[4][4];
#pragma unroll
        for (int a = 0; a < 4; ++a)
#pragma unroll
            for (int c = 0; c < 4; ++c) s[a][c] = 0.f;

#pragma unroll
        for (int r = 0; r < R; r += 4) {
            float4 qv[4], kv[4];
#pragma unroll
            for (int a = 0; a < 4; ++a)
                qv[a] = *reinterpret_cast<const float4*>(&q_sm[(4 * ti + a) * QP + r]);
#pragma unroll
            for (int c = 0; c < 4; ++c)
                kv[c] = *reinterpret_cast<const float4*>(&k_sm[(4 * tj + c) * QP + r]);
#pragma unroll
            for (int a = 0; a < 4; ++a)
#pragma unroll
                for (int c = 0; c < 4; ++c) {
                    s[a][c] = fmaf(qv[a].x, kv[c].x, s[a][c]);
                    s[a][c] = fmaf(qv[a].y, kv[c].y, s[a][c]);
                    s[a][c] = fmaf(qv[a].z, kv[c].z, s[a][c]);
                    s[a][c] = fmaf(qv[a].w, kv[c].w, s[a][c]);
                }
        }
        // softsign -> e_sm
#pragma unroll
        for (int a = 0; a < 4; ++a) {
            float4 e4;
            e4.x = s[a][0] / (1.f + fabsf(s[a][0]));
            e4.y = s[a][1] / (1.f + fabsf(s[a][1]));
            e4.z = s[a][2] / (1.f + fabsf(s[a][2]));
            e4.w = s[a][3] / (1.f + fabsf(s[a][3]));
            *reinterpret_cast<float4*>(&e_sm[(4 * ti + a) * QP + 4 * tj]) = e4;
        }
        __syncthreads();

        // --- delta_state partial (read-only on e_sm/st_sm) ---
        if (t < TM) {
            float d0 = 0.f;
#pragma unroll 8
            for (int j = 0; j < TN; ++j)
                d0 = fmaf(e_sm[t * QP + j], st_sm[j], d0);
            ds_sm[t] += d0;
        }

        // --- Epilogue GEMM: acc += E[rows][j] * v[j][cols] ---
#pragma unroll 4
        for (int j = 0; j < TN; ++j) {
            float e0 = e_sm[(ty     ) * QP + j];
            float e1 = e_sm[(ty + 16) * QP + j];
            float e2 = e_sm[(ty + 32) * QP + j];
            float e3 = e_sm[(ty + 48) * QP + j];
#pragma unroll
            for (int c = 0; c < 4; ++c) {
                float4 v = *reinterpret_cast<const float4*>(&v_sm[j * D + tx * 4 + c * 64]);
                acc[0][c].x = fmaf(e0, v.x, acc[0][c].x);
                acc[0][c].y = fmaf(e0, v.y, acc[0][c].y);
                acc[0][c].z = fmaf(e0, v.z, acc[0][c].z);
                acc[0][c].w = fmaf(e0, v.w, acc[0][c].w);
                acc[1][c].x = fmaf(e1, v.x, acc[1][c].x);
                acc[1][c].y = fmaf(e1, v.y, acc[1][c].y);
                acc[1][c].z = fmaf(e1, v.z, acc[1][c].z);
                acc[1][c].w = fmaf(e1, v.w, acc[1][c].w);
                acc[2][c].x = fmaf(e2, v.x, acc[2][c].x);
                acc[2][c].y = fmaf(e2, v.y, acc[2][c].y);
                acc[2][c].z = fmaf(e2, v.z, acc[2][c].z);
                acc[2][c].w = fmaf(e2, v.w, acc[2][c].w);
                acc[3][c].x = fmaf(e3, v.x, acc[3][c].x);
                acc[3][c].y = fmaf(e3, v.y, acc[3][c].y);
                acc[3][c].z = fmaf(e3, v.z, acc[3][c].z);
                acc[3][c].w = fmaf(e3, v.w, acc[3][c].w);
            }
        }
    }

    __syncthreads();
    if (t < TM) out_ds[b * N + n0 + t] = ds_sm[t];

#pragma unroll
    for (int a = 0; a < 4; ++a) {
        int row = n0 + ty + 16 * a;
        float* dst = out_dv + ((size_t)b * N + row) * D + tx * 4;
#pragma unroll
        for (int c = 0; c < 4; ++c)
            *reinterpret_cast<float4*>(dst + c * 64) = acc[a][c];
    }
}

}  // namespace

extern "C" void kernel_launch(void* const* d_in, const int* in_sizes, int n_in,
                              void* d_out, int out_size) {
    const float* state = (const float*)d_in[0];   // [B, N]
    const float* val   = (const float*)d_in[1];   // [B, N, D]
    const float* Wq    = (const float*)d_in[2];   // [D, R]
    const float* Wk    = (const float*)d_in[3];   // [D, R]

    float* out_ds = (float*)d_out;                // [B, N]
    float* out_dv = out_ds + B * N;               // [B, N, D]

    cudaFuncSetAttribute(prop_kernel, cudaFuncAttributeMaxDynamicSharedMemorySize, SMEM_BYTES);

    qk_kernel<<<B * N, 128>>>(val, Wq, Wk);
    prop_kernel<<<dim3(N / TM, B), 256, SMEM_BYTES>>>(state, val, out_ds, out_dv);
}

// round 2
// speedup vs baseline: 1.0596x; 1.0596x over previous
#include <cuda_runtime.h>

namespace {

constexpr int B = 2, N = 4096, D = 256, R = 64;
constexpr int TM = 64, TN = 64;
constexpr int QP = 68;               // padded row stride (floats): 17 float4, conflict-breaking
constexpr int THREADS = 512;

constexpr int SMEM_FLOATS = 3 * TM * QP + TN * D + TN + THREADS;
constexpr int SMEM_BYTES  = SMEM_FLOATS * 4;

__device__ float g_q[B * N * R];
__device__ float g_k[B * N * R];

typedef unsigned long long ull;

__device__ __forceinline__ ull pack2(float lo, float hi) {
    ull r;
    asm("mov.b64 %0, {%1, %2};" : "=l"(r) : "f"(lo), "f"(hi));
    return r;
}
__device__ __forceinline__ void unpack2(ull v, float& lo, float& hi) {
    asm("mov.b64 {%0, %1}, %2;" : "=f"(lo), "=f"(hi) : "l"(v));
}
// d += a * b  on packed f32x2 (Blackwell FFMA2; PTX-only, ptxas won't auto-fuse)
__device__ __forceinline__ void fma2(ull& d, ull a, ull b) {
    asm("fma.rn.f32x2 %0, %1, %2, %0;" : "+l"(d) : "l"(a), "l"(b));
}

// ---------------------------------------------------------------------------
// Kernel 1: q = val @ Wq, k = val @ Wk.  W staged in smem (64KB), 32 rows/block.
// blockIdx.x: bit0 selects Wq/Wk, rest selects the 32-row chunk of [B*N, D].
// ---------------------------------------------------------------------------
__global__ void __launch_bounds__(256) qk_kernel(const float* __restrict__ val,
                                                 const float* __restrict__ Wq,
                                                 const float* __restrict__ Wk) {
    extern __shared__ float qsm[];
    float* W_sm = qsm;                 // D*R floats (64KB)
    float* v_sm = qsm + D * R;         // 8*D floats

    const int t = threadIdx.x;
    const int which = blockIdx.x & 1;
    const int row0 = (blockIdx.x >> 1) * 32;

    const float* __restrict__ W = which ? Wk : Wq;
    float* __restrict__ out = which ? g_k : g_q;

    {
        const float4* wsrc = reinterpret_cast<const float4*>(W);
        float4* wdst = reinterpret_cast<float4*>(W_sm);
#pragma unroll
        for (int i = 0; i < (D * R / 4) / 256; ++i)
            wdst[t + i * 256] = wsrc[t + i * 256];
    }

    const int r  = 2 * (t & 31);       // output column pair
    const int rl = t >> 5;             // local row 0..7

#pragma unroll 1
    for (int it = 0; it < 4; ++it) {
        __syncthreads();               // v_sm reuse (and W ready on it==0)
        {
            const float4* vsrc =
                reinterpret_cast<const float4*>(val + (size_t)(row0 + it * 8) * D);
            float4* vdst = reinterpret_cast<float4*>(v_sm);
#pragma unroll
            for (int i = 0; i < 2; ++i)
                vdst[t + i * 256] = vsrc[t + i * 256];
        }
        __syncthreads();

        float2 acc = make_float2(0.f, 0.f);
#pragma unroll 8
        for (int d = 0; d < D; ++d) {
            float2 w2 = *reinterpret_cast<const float2*>(&W_sm[d * R + r]);
            float vv = v_sm[rl * D + d];
            acc.x = fmaf(vv, w2.x, acc.x);
            acc.y = fmaf(vv, w2.y, acc.y);
        }
        *reinterpret_cast<float2*>(&out[(size_t)(row0 + it * 8 + rl) * R + r]) = acc;
    }
}

// ---------------------------------------------------------------------------
// Kernel 2: fused scores -> softsign -> (edges@state, edges@val).
// 512 threads, TM=TN=64. edges never touch HBM. FFMA2 in both GEMM phases.
// ---------------------------------------------------------------------------
__global__ void __launch_bounds__(THREADS) prop_kernel(const float* __restrict__ state,
                                                       const float* __restrict__ val,
                                                       float* __restrict__ out_ds,
                                                       float* __restrict__ out_dv) {
    extern __shared__ float sm[];
    float* q_sm  = sm;                         // TM x QP
    float* k_sm  = q_sm + TM * QP;             // TN x QP
    float* e_sm  = k_sm + TN * QP;             // TM x QP
    float* v_sm  = e_sm + TM * QP;             // TN x D
    float* st_sm = v_sm + TN * D;              // TN
    float* red_sm = st_sm + TN;                // THREADS (ds reduction)

    const int b  = blockIdx.y;
    const int n0 = blockIdx.x * TM;
    const int t  = threadIdx.x;

    // Load q tile (TM*R/4 = 1024 float4 over 512 threads).
    {
        const float4* src = reinterpret_cast<const float4*>(g_q + ((size_t)b * N + n0) * R);
#pragma unroll
        for (int it = 0; it < 2; ++it) {
            int p = t + it * THREADS;
            int i = p >> 4, c = p & 15;        // R/4 = 16 float4 per row
            *reinterpret_cast<float4*>(&q_sm[i * QP + c * 4]) = src[p];
        }
    }

    // Score mapping: rows {lane, lane+32}, cols 4*wid..+3  (k loads broadcast per warp)
    const int lane = t & 31;
    const int wid  = t >> 5;
    // Epilogue mapping: rows {ty, ty+32}, float4-cols tx + 16*c
    const int ty = t >> 4;
    const int tx = t & 15;
    // delta_state mapping: row t&63, j-segment of 8
    const int ds_row = t & 63, ds_j0 = (t >> 6) * 8;

    float ds_acc = 0.f;
    ull acc2[2][4][2];                 // [rowsel][c][half] packed f32x2
#pragma unroll
    for (int a = 0; a < 2; ++a)
#pragma unroll
        for (int c = 0; c < 4; ++c) { acc2[a][c][0] = 0ull; acc2[a][c][1] = 0ull; }

#pragma unroll 1
    for (int m0 = 0; m0 < N; m0 += TN) {
        __syncthreads();               // previous tile's readers done (q ready on iter 0)

        // k tile (padded), v tile, state slice
        {
            const float4* src = reinterpret_cast<const float4*>(g_k + ((size_t)b * N + m0) * R);
#pragma unroll
            for (int it = 0; it < 2; ++it) {
                int p = t + it * THREADS;
                int i = p >> 4, c = p & 15;
                *reinterpret_cast<float4*>(&k_sm[i * QP + c * 4]) = src[p];
            }
        }
        {
            const float4* src = reinterpret_cast<const float4*>(val + ((size_t)b * N + m0) * D);
            float4* dst = reinterpret_cast<float4*>(v_sm);
#pragma unroll
            for (int it = 0; it < 8; ++it)
                dst[t + it * THREADS] = src[t + it * THREADS];
        }
        if (t < TN) st_sm[t] = state[b * N + m0 + t];
        __syncthreads();

        // --- Score phase (FFMA2 over r-pairs) ---
        ull s2[2][4];
#pragma unroll
        for (int a = 0; a < 2; ++a)
#pragma unroll
            for (int c = 0; c < 4; ++c) s2[a][c] = 0ull;

#pragma unroll
        for (int r = 0; r < R; r += 4) {
            ulonglong2 q0 = *reinterpret_cast<const ulonglong2*>(&q_sm[lane * QP + r]);
            ulonglong2 q1 = *reinterpret_cast<const ulonglong2*>(&q_sm[(lane + 32) * QP + r]);
#pragma unroll
            for (int c = 0; c < 4; ++c) {
                ulonglong2 kv = *reinterpret_cast<const ulonglong2*>(&k_sm[(4 * wid + c) * QP + r]);
                fma2(s2[0][c], q0.x, kv.x);
                fma2(s2[0][c], q0.y, kv.y);
                fma2(s2[1][c], q1.x, kv.x);
                fma2(s2[1][c], q1.y, kv.y);
            }
        }
        // horizontal add + softsign -> e_sm
        {
            float4 e0, e1;
            float lo, hi, s;
            unpack2(s2[0][0], lo, hi); s = lo + hi; e0.x = s / (1.f + fabsf(s));
            unpack2(s2[0][1], lo, hi); s = lo + hi; e0.y = s / (1.f + fabsf(s));
            unpack2(s2[0][2], lo, hi); s = lo + hi; e0.z = s / (1.f + fabsf(s));
            unpack2(s2[0][3], lo, hi); s = lo + hi; e0.w = s / (1.f + fabsf(s));
            unpack2(s2[1][0], lo, hi); s = lo + hi; e1.x = s / (1.f + fabsf(s));
            unpack2(s2[1][1], lo, hi); s = lo + hi; e1.y = s / (1.f + fabsf(s));
            unpack2(s2[1][2], lo, hi); s = lo + hi; e1.z = s / (1.f + fabsf(s));
            unpack2(s2[1][3], lo, hi); s = lo + hi; e1.w = s / (1.f + fabsf(s));
            *reinterpret_cast<float4*>(&e_sm[lane * QP + 4 * wid]) = e0;
            *reinterpret_cast<float4*>(&e_sm[(lane + 32) * QP + 4 * wid]) = e1;
        }
        __syncthreads();

        // --- delta_state partial: distributed over all 512 threads ---
#pragma unroll
        for (int jj = 0; jj < 8; ++jj)
            ds_acc = fmaf(e_sm[ds_row * QP + ds_j0 + jj], st_sm[ds_j0 + jj], ds_acc);

        // --- Epilogue GEMM (FFMA2): acc += E[rows][j] * v[j][cols] ---
#pragma unroll 4
        for (int j = 0; j < TN; ++j) {
            float e0f = e_sm[ty * QP + j];
            float e1f = e_sm[(ty + 32) * QP + j];
            ull e0 = pack2(e0f, e0f);
            ull e1 = pack2(e1f, e1f);
#pragma unroll
            for (int c = 0; c < 4; ++c) {
                ulonglong2 v2 =
                    *reinterpret_cast<const ulonglong2*>(&v_sm[j * D + tx * 4 + c * 64]);
                fma2(acc2[0][c][0], e0, v2.x);
                fma2(acc2[0][c][1], e0, v2.y);
                fma2(acc2[1][c][0], e1, v2.x);
                fma2(acc2[1][c][1], e1, v2.y);
            }
        }
    }

    // delta_state reduction (8 partials per row)
    red_sm[(t & 63) * 8 + (t >> 6)] = ds_acc;
    __syncthreads();
    if (t < TM) {
        float s = 0.f;
#pragma unroll
        for (int g = 0; g < 8; ++g) s += red_sm[t * 8 + g];
        out_ds[b * N + n0 + t] = s;
    }

    // delta_val writes
#pragma unroll
    for (int a = 0; a < 2; ++a) {
        int row = n0 + ty + 32 * a;
        float* dst = out_dv + ((size_t)b * N + row) * D + tx * 4;
#pragma unroll
        for (int c = 0; c < 4; ++c) {
            ulonglong2 v2;
            v2.x = acc2[a][c][0];
            v2.y = acc2[a][c][1];
            *reinterpret_cast<ulonglong2*>(dst + c * 64) = v2;
        }
    }
}

}  // namespace

extern "C" void kernel_launch(void* const* d_in, const int* in_sizes, int n_in,
                              void* d_out, int out_size) {
    const float* state = (const float*)d_in[0];   // [B, N]
    const float* val   = (const float*)d_in[1];   // [B, N, D]
    const float* Wq    = (const float*)d_in[2];   // [D, R]
    const float* Wk    = (const float*)d_in[3];   // [D, R]

    float* out_ds = (float*)d_out;                // [B, N]
    float* out_dv = out_ds + B * N;               // [B, N, D]

    constexpr int QK_SMEM = (D * R + 8 * D) * 4;
    cudaFuncSetAttribute(qk_kernel, cudaFuncAttributeMaxDynamicSharedMemorySize, QK_SMEM);
    cudaFuncSetAttribute(prop_kernel, cudaFuncAttributeMaxDynamicSharedMemorySize, SMEM_BYTES);

    qk_kernel<<<(B * N / 32) * 2, 256, QK_SMEM>>>(val, Wq, Wk);
    prop_kernel<<<dim3(N / TM, B), THREADS, SMEM_BYTES>>>(state, val, out_ds, out_dv);
}

// round 4
// speedup vs baseline: 2.6734x; 2.5231x over previous
#include <cuda_runtime.h>
#include <cstdint>

namespace {

constexpr int B = 2, N = 4096, D = 256, R = 64;
constexpr int TM = 64;         // n-rows per block
constexpr int TN = 64;         // m-tile
constexpr int THREADS = 256;   // 8 warps

// prop smem layout (float indices); stride 68 floats (272B, 16B-aligned)
constexpr int OFQ  = 0;                // 64 x 68
constexpr int OFK  = OFQ + 64 * 68;    // 64 x 68
constexpr int OFE  = OFK + 64 * 68;    // 64 x 68
constexpr int OFV  = OFE + 64 * 68;    // 256 x 68
constexpr int OFST = OFV + 256 * 68;   // 64
constexpr int OFRD = OFST + 64;        // 128
constexpr int SMEM_FLOATS = OFRD + 128;
constexpr int SMEM_BYTES  = SMEM_FLOATS * 4;

__device__ uint32_t g_q[B * N * R];    // tf32 bits, natural col order
__device__ uint32_t g_k[B * N * R];    // tf32 bits, k-permuted cols
__device__ uint32_t g_vt[B * D * N];   // tf32 bits, [b][d][m] with m k-permuted

// per-8-group k-permutation: w -> (w&3)*2 + (w>>2)
__host__ __device__ __forceinline__ int kslot(int c) {
    return (c & ~7) | (((c & 3) << 1) | ((c & 7) >> 2));
}

__device__ __forceinline__ uint32_t f2tf(float x) {
    uint32_t r;
    asm("cvt.rna.tf32.f32 %0, %1;" : "=r"(r) : "f"(x));
    return r;
}

__device__ __forceinline__ void mma_tf32(float (&d)[4], const uint32_t (&a)[4],
                                         uint32_t b0, uint32_t b1) {
    asm volatile(
        "mma.sync.aligned.m16n8k8.row.col.f32.tf32.tf32.f32 "
        "{%0,%1,%2,%3}, {%4,%5,%6,%7}, {%8,%9}, {%0,%1,%2,%3};"
        : "+f"(d[0]), "+f"(d[1]), "+f"(d[2]), "+f"(d[3])
        : "r"(a[0]), "r"(a[1]), "r"(a[2]), "r"(a[3]), "r"(b0), "r"(b1));
}

// ---------------------------------------------------------------------------
// Kernel 1: q = val@Wq (tf32, natural), k = val@Wk (tf32, k-permuted cols)
// ---------------------------------------------------------------------------
__global__ void __launch_bounds__(256) qk_kernel(const float* __restrict__ val,
                                                 const float* __restrict__ Wq,
                                                 const float* __restrict__ Wk) {
    extern __shared__ float qsm[];
    float* W_sm = qsm;                 // D*R
    float* v_sm = qsm + D * R;         // 8*D

    const int t = threadIdx.x;
    const int which = blockIdx.x & 1;
    const int row0 = (blockIdx.x >> 1) * 32;

    const float* __restrict__ W = which ? Wk : Wq;
    uint32_t* __restrict__ out = which ? g_k : g_q;

    {
        const float4* wsrc = reinterpret_cast<const float4*>(W);
        float4* wdst = reinterpret_cast<float4*>(W_sm);
#pragma unroll
        for (int i = 0; i < (D * R / 4) / 256; ++i)
            wdst[t + i * 256] = wsrc[t + i * 256];
    }

    const int r  = 2 * (t & 31);
    const int rl = t >> 5;

#pragma unroll 1
    for (int it = 0; it < 4; ++it) {
        __syncthreads();
        {
            const float4* vsrc =
                reinterpret_cast<const float4*>(val + (size_t)(row0 + it * 8) * D);
            float4* vdst = reinterpret_cast<float4*>(v_sm);
#pragma unroll
            for (int i = 0; i < 2; ++i)
                vdst[t + i * 256] = vsrc[t + i * 256];
        }
        __syncthreads();

        float2 acc = make_float2(0.f, 0.f);
#pragma unroll 8
        for (int d = 0; d < D; ++d) {
            float2 w2 = *reinterpret_cast<const float2*>(&W_sm[d * R + r]);
            float vv = v_sm[rl * D + d];
            acc.x = fmaf(vv, w2.x, acc.x);
            acc.y = fmaf(vv, w2.y, acc.y);
        }
        const size_t base = (size_t)(row0 + it * 8 + rl) * R;
        if (which) {
            out[base + kslot(r)]     = f2tf(acc.x);
            out[base + kslot(r + 1)] = f2tf(acc.y);
        } else {
            uint2 o = make_uint2(f2tf(acc.x), f2tf(acc.y));
            *reinterpret_cast<uint2*>(&out[base + r]) = o;
        }
    }
}

// ---------------------------------------------------------------------------
// Kernel 1b: g_vt[b][d][m'] = tf32(val[b][m][d]), m' k-permuted within 8-groups
// ---------------------------------------------------------------------------
__global__ void __launch_bounds__(256) vt_kernel(const float* __restrict__ val) {
    __shared__ float tile[64 * 65];
    const int b = blockIdx.z, m0 = blockIdx.x * 64, d0 = blockIdx.y * 64;
    const int t = threadIdx.x;

#pragma unroll
    for (int it = 0; it < 4; ++it) {
        int p = t + it * 256;              // 1024 float4
        int row = p >> 4, c4 = p & 15;     // m-row, d float4-col
        float4 v = *reinterpret_cast<const float4*>(
            val + ((size_t)b * N + m0 + row) * D + d0 + 4 * c4);
        tile[(4 * c4 + 0) * 65 + row] = v.x;
        tile[(4 * c4 + 1) * 65 + row] = v.y;
        tile[(4 * c4 + 2) * 65 + row] = v.z;
        tile[(4 * c4 + 3) * 65 + row] = v.w;
    }
    __syncthreads();

#pragma unroll
    for (int it = 0; it < 4; ++it) {
        int p = t + it * 256;
        int drow = p >> 4, mc4 = p & 15;
        uint4 o;
        uint32_t* op = reinterpret_cast<uint32_t*>(&o);
#pragma unroll
        for (int j = 0; j < 4; ++j) {
            int s = 4 * mc4 + j;
            int so = s & 7;
            int w = (so >> 1) + ((so & 1) << 2);   // inverse perm
            op[j] = f2tf(tile[drow * 65 + (s & ~7) + w]);
        }
        *reinterpret_cast<uint4*>(
            &g_vt[((size_t)b * D + d0 + drow) * N + m0 + 4 * mc4]) = o;
    }
}

// ---------------------------------------------------------------------------
// Kernel 2: fused scores -> softsign -> (edges@state, edges@val) via mma.sync
// Block: 64 n-rows, 8 warps (wr=wid&3 row quarter, wc=wid>>2 col half).
// ---------------------------------------------------------------------------
__global__ void __launch_bounds__(THREADS) prop_kernel(const float* __restrict__ state,
                                                       float* __restrict__ out_ds,
                                                       float* __restrict__ out_dv) {
    extern __shared__ float sm[];
    uint32_t* smU = reinterpret_cast<uint32_t*>(sm);

    const int b  = blockIdx.y;
    const int n0 = blockIdx.x * TM;
    const int t  = threadIdx.x;
    const int wid = t >> 5, lane = t & 31;
    const int g = lane >> 2, tg = lane & 3;
    const int wr = wid & 3, wc = wid >> 2;

    // E-write slot offsets for cols 2tg, 2tg+1
    const int se = (((2 * tg) & 3) << 1) | (tg >> 1);
    const int so = ((((2 * tg + 1) & 3)) << 1) | ((2 * tg + 1) >> 2);

    // ---- stage Q tile (straight uint4 copy, stride 68)
    {
        const uint4* src = reinterpret_cast<const uint4*>(g_q + ((size_t)b * N + n0) * R);
#pragma unroll
        for (int it = 0; it < 4; ++it) {
            int p = t + it * THREADS;
            int row = p >> 4, c = p & 15;
            *reinterpret_cast<uint4*>(&sm[OFQ + row * 68 + 4 * c]) = src[p];
        }
    }
    __syncthreads();

    // ---- preload Q A-fragments (persist all 64 m-tiles)
    uint32_t aq[8][4];
    {
        const int r0 = OFQ + (16 * wr + g) * 68;
        const int r1 = r0 + 8 * 68;
#pragma unroll
        for (int ks = 0; ks < 8; ++ks) {
            aq[ks][0] = smU[r0 + 8 * ks + tg];
            aq[ks][1] = smU[r1 + 8 * ks + tg];
            aq[ks][2] = smU[r0 + 8 * ks + tg + 4];
            aq[ks][3] = smU[r1 + 8 * ks + tg + 4];
        }
    }

    float dv[16][4];
#pragma unroll
    for (int nt = 0; nt < 16; ++nt)
#pragma unroll
        for (int j = 0; j < 4; ++j) dv[nt][j] = 0.f;
    float ds0 = 0.f, ds1 = 0.f;

#pragma unroll 1
    for (int i = 0; i < N / TN; ++i) {
        const int m0 = i * TN;
        __syncthreads();   // k/v/e free (iter 0: after aq preload)

        // K tile (straight copy)
        {
            const uint4* src = reinterpret_cast<const uint4*>(g_k + ((size_t)b * N + m0) * R);
#pragma unroll
            for (int it = 0; it < 4; ++it) {
                int p = t + it * THREADS;
                int row = p >> 4, c = p & 15;
                *reinterpret_cast<uint4*>(&sm[OFK + row * 68 + 4 * c]) = src[p];
            }
        }
        // VT tile (256 d-rows x 64 m)
        {
            const uint4* src = reinterpret_cast<const uint4*>(g_vt + (size_t)b * D * N);
#pragma unroll
            for (int it = 0; it < 16; ++it) {
                int p = t + it * THREADS;
                int row = p >> 4, c = p & 15;
                *reinterpret_cast<uint4*>(&sm[OFV + row * 68 + 4 * c]) =
                    src[(size_t)row * (N / 4) + m0 / 4 + c];
            }
        }
        if (t < TN) sm[OFST + t] = state[b * N + m0 + t];
        __syncthreads();

        // ---- MMA1: S(16 x 32 per warp) = Q . K^T
        float sacc[4][4];
#pragma unroll
        for (int nt = 0; nt < 4; ++nt)
#pragma unroll
            for (int j = 0; j < 4; ++j) sacc[nt][j] = 0.f;

#pragma unroll
        for (int ks = 0; ks < 8; ++ks) {
#pragma unroll
            for (int nt = 0; nt < 4; ++nt) {
                uint2 bb = *reinterpret_cast<const uint2*>(
                    &sm[OFK + (32 * wc + 8 * nt + g) * 68 + 8 * ks + 2 * tg]);
                mma_tf32(sacc[nt], aq[ks], bb.x, bb.y);
            }
        }

        // ---- softsign + delta_state + E(tf32, permuted) to smem
#pragma unroll
        for (int nt = 0; nt < 4; ++nt) {
            const int c0 = 32 * wc + 8 * nt + 2 * tg;
            float e00 = __fdividef(sacc[nt][0], 1.f + fabsf(sacc[nt][0]));
            float e01 = __fdividef(sacc[nt][1], 1.f + fabsf(sacc[nt][1]));
            float e10 = __fdividef(sacc[nt][2], 1.f + fabsf(sacc[nt][2]));
            float e11 = __fdividef(sacc[nt][3], 1.f + fabsf(sacc[nt][3]));
            float s0 = sm[OFST + c0], s1 = sm[OFST + c0 + 1];
            ds0 = fmaf(e00, s0, fmaf(e01, s1, ds0));
            ds1 = fmaf(e10, s0, fmaf(e11, s1, ds1));
            const int basec = 32 * wc + 8 * nt;
            const int er0 = OFE + (16 * wr + g) * 68 + basec;
            const int er1 = er0 + 8 * 68;
            smU[er0 + se] = f2tf(e00);
            smU[er0 + so] = f2tf(e01);
            smU[er1 + se] = f2tf(e10);
            smU[er1 + so] = f2tf(e11);
        }
        __syncthreads();

        // ---- MMA2: DV(16 x 128 per warp) += E . V
#pragma unroll
        for (int ks = 0; ks < 8; ++ks) {
            uint2 ae0 = *reinterpret_cast<const uint2*>(
                &sm[OFE + (16 * wr + g) * 68 + 8 * ks + 2 * tg]);
            uint2 ae1 = *reinterpret_cast<const uint2*>(
                &sm[OFE + (16 * wr + g + 8) * 68 + 8 * ks + 2 * tg]);
            uint32_t a[4] = {ae0.x, ae1.x, ae0.y, ae1.y};
#pragma unroll
            for (int nt = 0; nt < 16; ++nt) {
                uint2 bb = *reinterpret_cast<const uint2*>(
                    &sm[OFV + (128 * wc + 8 * nt + g) * 68 + 8 * ks + 2 * tg]);
                mma_tf32(dv[nt], a, bb.x, bb.y);
            }
        }
    }

    // ---- epilogue: DV writes
    {
        const int rowA = n0 + 16 * wr + g;
        const int rowB = rowA + 8;
        float* dA = out_dv + ((size_t)b * N + rowA) * D;
        float* dB = out_dv + ((size_t)b * N + rowB) * D;
#pragma unroll
        for (int nt = 0; nt < 16; ++nt) {
            const int col = 128 * wc + 8 * nt + 2 * tg;
            *reinterpret_cast<float2*>(dA + col) = make_float2(dv[nt][0], dv[nt][1]);
            *reinterpret_cast<float2*>(dB + col) = make_float2(dv[nt][2], dv[nt][3]);
        }
    }

    // ---- delta_state reduction
    ds0 += __shfl_xor_sync(0xFFFFFFFF, ds0, 1);
    ds0 += __shfl_xor_sync(0xFFFFFFFF, ds0, 2);
    ds1 += __shfl_xor_sync(0xFFFFFFFF, ds1, 1);
    ds1 += __shfl_xor_sync(0xFFFFFFFF, ds1, 2);
    __syncthreads();
    if (tg == 0) {
        sm[OFRD + (16 * wr + g) * 2 + wc]     = ds0;
        sm[OFRD + (16 * wr + g + 8) * 2 + wc] = ds1;
    }
    __syncthreads();
    if (t < TM)
        out_ds[b * N + n0 + t] = sm[OFRD + t * 2] + sm[OFRD + t * 2 + 1];
}

}  // namespace

extern "C" void kernel_launch(void* const* d_in, const int* in_sizes, int n_in,
                              void* d_out, int out_size) {
    const float* state = (const float*)d_in[0];   // [B, N]
    const float* val   = (const float*)d_in[1];   // [B, N, D]
    const float* Wq    = (const float*)d_in[2];   // [D, R]
    const float* Wk    = (const float*)d_in[3];   // [D, R]

    float* out_ds = (float*)d_out;                // [B, N]
    float* out_dv = out_ds + B * N;               // [B, N, D]

    constexpr int QK_SMEM = (D * R + 8 * D) * 4;
    cudaFuncSetAttribute(qk_kernel, cudaFuncAttributeMaxDynamicSharedMemorySize, QK_SMEM);
    cudaFuncSetAttribute(prop_kernel, cudaFuncAttributeMaxDynamicSharedMemorySize, SMEM_BYTES);

    qk_kernel<<<(B * N / 32) * 2, 256, QK_SMEM>>>(val, Wq, Wk);
    vt_kernel<<<dim3(N / 64, D / 64, B), 256>>>(val);
    prop_kernel<<<dim3(N / TM, B), THREADS, SMEM_BYTES>>>(state, out_ds, out_dv);
}

// round 5
// speedup vs baseline: 3.5378x; 1.3233x over previous
#include <cuda_runtime.h>
#include <cstdint>

namespace {

constexpr int B = 2, N = 4096, D = 256, R = 64;
constexpr int TM = 64;         // n-rows per block
constexpr int TN = 64;         // m-tile
constexpr int THREADS = 256;   // 8 warps

// prop smem float-index layout (row stride 68 floats = 272B)
constexpr int OFQ  = 0;                    // 64 x 68
constexpr int OFE  = OFQ + 64 * 68;        // 64 x 68
constexpr int OFK0 = OFE + 64 * 68;        // 64 x 68
constexpr int OFK1 = OFK0 + 64 * 68;
constexpr int OFV0 = OFK1 + 64 * 68;       // 256 x 68
constexpr int OFV1 = OFV0 + 256 * 68;
constexpr int OFST0 = OFV1 + 256 * 68;     // 64
constexpr int OFST1 = OFST0 + 64;
constexpr int OFRD  = OFST1 + 64;          // 128
constexpr int SMEM_FLOATS = OFRD + 128;
constexpr int SMEM_BYTES  = SMEM_FLOATS * 4;   // 209920

__device__ uint32_t g_q[B * N * R];    // tf32 bits, natural col order
__device__ uint32_t g_k[B * N * R];    // tf32 bits, k-permuted cols
__device__ uint32_t g_vt[B * D * N];   // tf32 bits, [b][d][m], m k-permuted

__host__ __device__ __forceinline__ int kslot(int c) {
    return (c & ~7) | (((c & 3) << 1) | ((c & 7) >> 2));
}

__device__ __forceinline__ uint32_t f2tf(float x) {
    uint32_t r;
    asm("cvt.rna.tf32.f32 %0, %1;" : "=r"(r) : "f"(x));
    return r;
}

__device__ __forceinline__ uint32_t smem_u32(const void* p) {
    uint32_t a;
    asm("{ .reg .u64 t; cvta.to.shared.u64 t, %1; cvt.u32.u64 %0, t; }" : "=r"(a) : "l"(p));
    return a;
}

__device__ __forceinline__ void cp16(uint32_t dst, const void* src) {
    asm volatile("cp.async.cg.shared.global [%0], [%1], 16;" :: "r"(dst), "l"(src));
}
__device__ __forceinline__ void cp_commit() {
    asm volatile("cp.async.commit_group;");
}
__device__ __forceinline__ void cp_wait0() {
    asm volatile("cp.async.wait_group 0;");
}

__device__ __forceinline__ void mma_tf32(float (&d)[4], const uint32_t (&a)[4],
                                         uint32_t b0, uint32_t b1) {
    asm volatile(
        "mma.sync.aligned.m16n8k8.row.col.f32.tf32.tf32.f32 "
        "{%0,%1,%2,%3}, {%4,%5,%6,%7}, {%8,%9}, {%0,%1,%2,%3};"
        : "+f"(d[0]), "+f"(d[1]), "+f"(d[2]), "+f"(d[3])
        : "r"(a[0]), "r"(a[1]), "r"(a[2]), "r"(a[3]), "r"(b0), "r"(b1));
}

// ---------------------------------------------------------------------------
// Kernel 1: q = val@Wq (tf32, natural), k = val@Wk (tf32, k-permuted cols)
// 32 rows/block; thread = 4 rows x 2 cols; float4 d-steps.
// ---------------------------------------------------------------------------
__global__ void __launch_bounds__(256) qk_kernel(const float* __restrict__ val,
                                                 const float* __restrict__ Wq,
                                                 const float* __restrict__ Wk) {
    extern __shared__ float qsm[];
    float* W_sm = qsm;                 // D*R = 16384
    float* v_sm = qsm + D * R;         // 32*D = 8192

    const int t = threadIdx.x;
    const int which = blockIdx.x & 1;
    const int row0 = (blockIdx.x >> 1) * 32;

    const float* __restrict__ W = which ? Wk : Wq;
    uint32_t* __restrict__ out = which ? g_k : g_q;

    {
        const float4* wsrc = reinterpret_cast<const float4*>(W);
        float4* wdst = reinterpret_cast<float4*>(W_sm);
#pragma unroll
        for (int i = 0; i < 16; ++i)
            wdst[t + i * 256] = wsrc[t + i * 256];
        const float4* vsrc = reinterpret_cast<const float4*>(val + (size_t)row0 * D);
        float4* vdst = reinterpret_cast<float4*>(v_sm);
#pragma unroll
        for (int i = 0; i < 8; ++i)
            vdst[t + i * 256] = vsrc[t + i * 256];
    }
    __syncthreads();

    const int r  = 2 * (t & 31);       // col pair
    const int rg = t >> 5;             // row group: rows rg*4 + {0..3}

    float acc[4][2];
#pragma unroll
    for (int j = 0; j < 4; ++j) { acc[j][0] = 0.f; acc[j][1] = 0.f; }

#pragma unroll 4
    for (int d = 0; d < D; d += 4) {
        float2 w0 = *reinterpret_cast<const float2*>(&W_sm[(d + 0) * R + r]);
        float2 w1 = *reinterpret_cast<const float2*>(&W_sm[(d + 1) * R + r]);
        float2 w2 = *reinterpret_cast<const float2*>(&W_sm[(d + 2) * R + r]);
        float2 w3 = *reinterpret_cast<const float2*>(&W_sm[(d + 3) * R + r]);
#pragma unroll
        for (int j = 0; j < 4; ++j) {
            float4 v = *reinterpret_cast<const float4*>(&v_sm[(rg * 4 + j) * D + d]);
            acc[j][0] = fmaf(v.x, w0.x, acc[j][0]);
            acc[j][1] = fmaf(v.x, w0.y, acc[j][1]);
            acc[j][0] = fmaf(v.y, w1.x, acc[j][0]);
            acc[j][1] = fmaf(v.y, w1.y, acc[j][1]);
            acc[j][0] = fmaf(v.z, w2.x, acc[j][0]);
            acc[j][1] = fmaf(v.z, w2.y, acc[j][1]);
            acc[j][0] = fmaf(v.w, w3.x, acc[j][0]);
            acc[j][1] = fmaf(v.w, w3.y, acc[j][1]);
        }
    }

#pragma unroll
    for (int j = 0; j < 4; ++j) {
        const size_t base = (size_t)(row0 + rg * 4 + j) * R;
        if (which) {
            out[base + kslot(r)]     = f2tf(acc[j][0]);
            out[base + kslot(r + 1)] = f2tf(acc[j][1]);
        } else {
            uint2 o = make_uint2(f2tf(acc[j][0]), f2tf(acc[j][1]));
            *reinterpret_cast<uint2*>(&out[base + r]) = o;
        }
    }
}

// ---------------------------------------------------------------------------
// Kernel 1b: g_vt[b][d][m'] = tf32(val[b][m][d]), m' k-permuted in 8-groups
// ---------------------------------------------------------------------------
__global__ void __launch_bounds__(256) vt_kernel(const float* __restrict__ val) {
    __shared__ float tile[64 * 65];
    const int b = blockIdx.z, m0 = blockIdx.x * 64, d0 = blockIdx.y * 64;
    const int t = threadIdx.x;

#pragma unroll
    for (int it = 0; it < 4; ++it) {
        int p = t + it * 256;
        int row = p >> 4, c4 = p & 15;
        float4 v = *reinterpret_cast<const float4*>(
            val + ((size_t)b * N + m0 + row) * D + d0 + 4 * c4);
        tile[(4 * c4 + 0) * 65 + row] = v.x;
        tile[(4 * c4 + 1) * 65 + row] = v.y;
        tile[(4 * c4 + 2) * 65 + row] = v.z;
        tile[(4 * c4 + 3) * 65 + row] = v.w;
    }
    __syncthreads();

#pragma unroll
    for (int it = 0; it < 4; ++it) {
        int p = t + it * 256;
        int drow = p >> 4, mc4 = p & 15;
        uint4 o;
        uint32_t* op = reinterpret_cast<uint32_t*>(&o);
#pragma unroll
        for (int j = 0; j < 4; ++j) {
            int s = 4 * mc4 + j;
            int so = s & 7;
            int w = (so >> 1) + ((so & 1) << 2);
            op[j] = f2tf(tile[drow * 65 + (s & ~7) + w]);
        }
        *reinterpret_cast<uint4*>(
            &g_vt[((size_t)b * D + d0 + drow) * N + m0 + 4 * mc4]) = o;
    }
}

// ---------------------------------------------------------------------------
// Kernel 2: fused scores -> softsign -> (edges@state, edges@val) via mma.sync
// Double-buffered cp.async pipeline; MMA2 warp tile 32x64.
// ---------------------------------------------------------------------------
__global__ void __launch_bounds__(THREADS) prop_kernel(const float* __restrict__ state,
                                                       float* __restrict__ out_ds,
                                                       float* __restrict__ out_dv) {
    extern __shared__ float sm[];
    uint32_t* smU = reinterpret_cast<uint32_t*>(sm);
    const uint32_t sbase = smem_u32(sm);

    const int b  = blockIdx.y;
    const int n0 = blockIdx.x * TM;
    const int t  = threadIdx.x;
    const int wid = t >> 5, lane = t & 31;
    const int g = lane >> 2, tg = lane & 3;
    const int wr = wid & 3, wc = wid >> 2;        // MMA1 mapping
    const int wr2 = wid & 1, wc2 = wid >> 1;      // MMA2 mapping (32x64)

    const int se = (((2 * tg) & 3) << 1) | (tg >> 1);
    const int so = ((((2 * tg + 1) & 3)) << 1) | ((2 * tg + 1) >> 2);

    const uint32_t* gk_b = g_k + (size_t)b * N * R;
    const uint32_t* gvt_b = g_vt + (size_t)b * D * N;
    const float* st_b = state + (size_t)b * N;

    // ---- stage Q tile
    {
        const uint4* src = reinterpret_cast<const uint4*>(g_q + ((size_t)b * N + n0) * R);
#pragma unroll
        for (int it = 0; it < 4; ++it) {
            int p = t + it * THREADS;
            int row = p >> 4, c = p & 15;
            *reinterpret_cast<uint4*>(&sm[OFQ + row * 68 + 4 * c]) = src[p];
        }
    }

    // ---- prefetch tile 0 (cp.async), then finish Q staging with barrier
    auto prefetch = [&](int m0, int buf) {
        const int ofk = buf ? OFK1 : OFK0;
        const int ofv = buf ? OFV1 : OFV0;
        const int ofst = buf ? OFST1 : OFST0;
#pragma unroll
        for (int it = 0; it < 4; ++it) {
            int p = t + it * THREADS;
            int row = p >> 4, c = p & 15;
            cp16(sbase + (uint32_t)(ofk + row * 68 + 4 * c) * 4u,
                 gk_b + (size_t)(m0 + row) * R + 4 * c);
        }
#pragma unroll
        for (int it = 0; it < 16; ++it) {
            int p = t + it * THREADS;
            int row = p >> 4, c = p & 15;
            cp16(sbase + (uint32_t)(ofv + row * 68 + 4 * c) * 4u,
                 gvt_b + (size_t)row * N + m0 + 4 * c);
        }
        if (t < 16)
            cp16(sbase + (uint32_t)(ofst + 4 * t) * 4u, st_b + m0 + 4 * t);
    };

    prefetch(0, 0);
    cp_commit();
    __syncthreads();   // Q visible

    // ---- preload Q A-fragments
    uint32_t aq[8][4];
    {
        const int r0 = OFQ + (16 * wr + g) * 68;
        const int r1 = r0 + 8 * 68;
#pragma unroll
        for (int ks = 0; ks < 8; ++ks) {
            aq[ks][0] = smU[r0 + 8 * ks + tg];
            aq[ks][1] = smU[r1 + 8 * ks + tg];
            aq[ks][2] = smU[r0 + 8 * ks + tg + 4];
            aq[ks][3] = smU[r1 + 8 * ks + tg + 4];
        }
    }

    float dv[2][8][4];
#pragma unroll
    for (int mt = 0; mt < 2; ++mt)
#pragma unroll
        for (int nt = 0; nt < 8; ++nt)
#pragma unroll
            for (int j = 0; j < 4; ++j) dv[mt][nt][j] = 0.f;
    float ds0 = 0.f, ds1 = 0.f;

#pragma unroll 1
    for (int i = 0; i < N / TN; ++i) {
        const int buf = i & 1;
        const int ofk = buf ? OFK1 : OFK0;
        const int ofv = buf ? OFV1 : OFV0;
        const int ofst = buf ? OFST1 : OFST0;

        cp_wait0();
        __syncthreads();   // tile i resident; prev iter fully done

        if (i + 1 < N / TN) {
            prefetch((i + 1) * TN, buf ^ 1);
            cp_commit();
        }

        // ---- MMA1: S(16x32 per warp) = Q . K^T
        float sacc[4][4];
#pragma unroll
        for (int nt = 0; nt < 4; ++nt)
#pragma unroll
            for (int j = 0; j < 4; ++j) sacc[nt][j] = 0.f;

#pragma unroll
        for (int ks = 0; ks < 8; ++ks) {
#pragma unroll
            for (int nt = 0; nt < 4; ++nt) {
                uint2 bb = *reinterpret_cast<const uint2*>(
                    &sm[ofk + (32 * wc + 8 * nt + g) * 68 + 8 * ks + 2 * tg]);
                mma_tf32(sacc[nt], aq[ks], bb.x, bb.y);
            }
        }

        // ---- softsign + delta_state + E(tf32, permuted slots) to smem
#pragma unroll
        for (int nt = 0; nt < 4; ++nt) {
            const int c0 = 32 * wc + 8 * nt + 2 * tg;
            float e00 = __fdividef(sacc[nt][0], 1.f + fabsf(sacc[nt][0]));
            float e01 = __fdividef(sacc[nt][1], 1.f + fabsf(sacc[nt][1]));
            float e10 = __fdividef(sacc[nt][2], 1.f + fabsf(sacc[nt][2]));
            float e11 = __fdividef(sacc[nt][3], 1.f + fabsf(sacc[nt][3]));
            float s0 = sm[ofst + c0], s1 = sm[ofst + c0 + 1];
            ds0 = fmaf(e00, s0, fmaf(e01, s1, ds0));
            ds1 = fmaf(e10, s0, fmaf(e11, s1, ds1));
            const int basec = 32 * wc + 8 * nt;
            const int er0 = OFE + (16 * wr + g) * 68 + basec;
            const int er1 = er0 + 8 * 68;
            smU[er0 + se] = f2tf(e00);
            smU[er0 + so] = f2tf(e01);
            smU[er1 + se] = f2tf(e10);
            smU[er1 + so] = f2tf(e11);
        }
        __syncthreads();

        // ---- MMA2: DV(32x64 per warp) += E . V
#pragma unroll
        for (int ks = 0; ks < 8; ++ks) {
            uint32_t a[2][4];
#pragma unroll
            for (int mt = 0; mt < 2; ++mt) {
                const int rbase = 32 * wr2 + 16 * mt;
                uint2 ae0 = *reinterpret_cast<const uint2*>(
                    &sm[OFE + (rbase + g) * 68 + 8 * ks + 2 * tg]);
                uint2 ae1 = *reinterpret_cast<const uint2*>(
                    &sm[OFE + (rbase + g + 8) * 68 + 8 * ks + 2 * tg]);
                a[mt][0] = ae0.x; a[mt][1] = ae1.x; a[mt][2] = ae0.y; a[mt][3] = ae1.y;
            }
#pragma unroll
            for (int nt = 0; nt < 8; ++nt) {
                uint2 bb = *reinterpret_cast<const uint2*>(
                    &sm[ofv + (64 * wc2 + 8 * nt + g) * 68 + 8 * ks + 2 * tg]);
                mma_tf32(dv[0][nt], a[0], bb.x, bb.y);
                mma_tf32(dv[1][nt], a[1], bb.x, bb.y);
            }
        }
    }

    // ---- epilogue: DV writes
#pragma unroll
    for (int mt = 0; mt < 2; ++mt) {
        const int rowA = n0 + 32 * wr2 + 16 * mt + g;
        float* dA = out_dv + ((size_t)b * N + rowA) * D;
        float* dB = dA + 8 * D;
#pragma unroll
        for (int nt = 0; nt < 8; ++nt) {
            const int col = 64 * wc2 + 8 * nt + 2 * tg;
            *reinterpret_cast<float2*>(dA + col) = make_float2(dv[mt][nt][0], dv[mt][nt][1]);
            *reinterpret_cast<float2*>(dB + col) = make_float2(dv[mt][nt][2], dv[mt][nt][3]);
        }
    }

    // ---- delta_state reduction
    ds0 += __shfl_xor_sync(0xFFFFFFFF, ds0, 1);
    ds0 += __shfl_xor_sync(0xFFFFFFFF, ds0, 2);
    ds1 += __shfl_xor_sync(0xFFFFFFFF, ds1, 1);
    ds1 += __shfl_xor_sync(0xFFFFFFFF, ds1, 2);
    __syncthreads();
    if (tg == 0) {
        sm[OFRD + (16 * wr + g) * 2 + wc]     = ds0;
        sm[OFRD + (16 * wr + g + 8) * 2 + wc] = ds1;
    }
    __syncthreads();
    if (t < TM)
        out_ds[b * N + n0 + t] = sm[OFRD + t * 2] + sm[OFRD + t * 2 + 1];
}

}  // namespace

extern "C" void kernel_launch(void* const* d_in, const int* in_sizes, int n_in,
                              void* d_out, int out_size) {
    const float* state = (const float*)d_in[0];   // [B, N]
    const float* val   = (const float*)d_in[1];   // [B, N, D]
    const float* Wq    = (const float*)d_in[2];   // [D, R]
    const float* Wk    = (const float*)d_in[3];   // [D, R]

    float* out_ds = (float*)d_out;                // [B, N]
    float* out_dv = out_ds + B * N;               // [B, N, D]

    constexpr int QK_SMEM = (D * R + 32 * D) * 4;   // 96KB
    cudaFuncSetAttribute(qk_kernel, cudaFuncAttributeMaxDynamicSharedMemorySize, QK_SMEM);
    cudaFuncSetAttribute(prop_kernel, cudaFuncAttributeMaxDynamicSharedMemorySize, SMEM_BYTES);

    qk_kernel<<<(B * N / 32) * 2, 256, QK_SMEM>>>(val, Wq, Wk);
    vt_kernel<<<dim3(N / 64, D / 64, B), 256>>>(val);
    prop_kernel<<<dim3(N / TM, B), THREADS, SMEM_BYTES>>>(state, out_ds, out_dv);
}

// round 6
// speedup vs baseline: 4.1331x; 1.1683x over previous
#include <cuda_runtime.h>
#include <cstdint>

namespace {

constexpr int B = 2, N = 4096, D = 256, R = 64;
constexpr int TM = 64;         // n-rows per block
constexpr int TN = 32;         // m-tile
constexpr int THREADS = 512;   // 16 warps

// prop smem float-index layout. Strides: K=72, VT/E=40 (mod 32 == 8 -> no
// bank conflicts on 8-row fragment loads), all 16B-aligned.
constexpr int OFE   = 0;                     // 64 x 40
constexpr int OFK0  = OFE + 64 * 40;         // 32 x 72
constexpr int OFK1  = OFK0 + 32 * 72;
constexpr int OFV0  = OFK1 + 32 * 72;        // 256 x 40
constexpr int OFV1  = OFV0 + 256 * 40;
constexpr int OFST0 = OFV1 + 256 * 40;       // 32
constexpr int OFST1 = OFST0 + 32;
constexpr int OFRD  = OFST1 + 32;            // 256
constexpr int SMEM_FLOATS = OFRD + 256;
constexpr int SMEM_BYTES  = SMEM_FLOATS * 4;   // ~109.5 KB -> 1 block/SM, 16 warps

__device__ uint32_t g_q[B * N * R];    // tf32 bits, natural col order
__device__ uint32_t g_k[B * N * R];    // tf32 bits, k-permuted cols
__device__ uint32_t g_vt[B * D * N];   // tf32 bits, [b][d][m], m k-permuted

__host__ __device__ __forceinline__ int kslot(int c) {
    return (c & ~7) | (((c & 3) << 1) | ((c & 7) >> 2));
}

__device__ __forceinline__ uint32_t f2tf(float x) {
    uint32_t r;
    asm("cvt.rna.tf32.f32 %0, %1;" : "=r"(r) : "f"(x));
    return r;
}

__device__ __forceinline__ uint32_t smem_u32(const void* p) {
    uint32_t a;
    asm("{ .reg .u64 t; cvta.to.shared.u64 t, %1; cvt.u32.u64 %0, t; }" : "=r"(a) : "l"(p));
    return a;
}

__device__ __forceinline__ void cp16(uint32_t dst, const void* src) {
    asm volatile("cp.async.cg.shared.global [%0], [%1], 16;" :: "r"(dst), "l"(src));
}
__device__ __forceinline__ void cp_commit() { asm volatile("cp.async.commit_group;"); }
__device__ __forceinline__ void cp_wait0()  { asm volatile("cp.async.wait_group 0;"); }

__device__ __forceinline__ void mma_tf32(float (&d)[4], const uint32_t (&a)[4],
                                         uint32_t b0, uint32_t b1) {
    asm volatile(
        "mma.sync.aligned.m16n8k8.row.col.f32.tf32.tf32.f32 "
        "{%0,%1,%2,%3}, {%4,%5,%6,%7}, {%8,%9}, {%0,%1,%2,%3};"
        : "+f"(d[0]), "+f"(d[1]), "+f"(d[2]), "+f"(d[3])
        : "r"(a[0]), "r"(a[1]), "r"(a[2]), "r"(a[3]), "r"(b0), "r"(b1));
}

// ---------------------------------------------------------------------------
// Kernel 1: q = val@Wq (natural), k = val@Wk (k-permuted). 128 rows/block,
// W staged once, v row-batches double-buffered via cp.async.
// ---------------------------------------------------------------------------
__global__ void __launch_bounds__(256) qk_kernel(const float* __restrict__ val,
                                                 const float* __restrict__ Wq,
                                                 const float* __restrict__ Wk) {
    extern __shared__ float qsm[];
    float* W_sm = qsm;                   // D*R = 16384
    float* v_sm = qsm + D * R;           // 2 x 32*D = 2 x 8192
    const uint32_t sbase = smem_u32(qsm);
    const uint32_t vbase = sbase + D * R * 4;

    const int t = threadIdx.x;
    const int which = blockIdx.x & 1;
    const int row0 = (blockIdx.x >> 1) * 128;

    const float* __restrict__ W = which ? Wk : Wq;
    uint32_t* __restrict__ out = which ? g_k : g_q;

    // prefetch v batch 0
    {
        const float* src = val + (size_t)row0 * D;
#pragma unroll
        for (int i = 0; i < 8; ++i)
            cp16(vbase + (uint32_t)(t + i * 256) * 16u, src + 4 * (t + i * 256));
        cp_commit();
    }
    // stage W
    {
        const float4* wsrc = reinterpret_cast<const float4*>(W);
        float4* wdst = reinterpret_cast<float4*>(W_sm);
#pragma unroll
        for (int i = 0; i < 16; ++i)
            wdst[t + i * 256] = wsrc[t + i * 256];
    }

    const int r  = 2 * (t & 31);
    const int rg = t >> 5;

#pragma unroll 1
    for (int bat = 0; bat < 4; ++bat) {
        const int buf = bat & 1;
        cp_wait0();
        __syncthreads();                 // v[buf] ready; v[buf^1] free

        if (bat + 1 < 4) {
            const float* src = val + (size_t)(row0 + (bat + 1) * 32) * D;
            const uint32_t dst = vbase + (uint32_t)(buf ^ 1) * 32768u;
#pragma unroll
            for (int i = 0; i < 8; ++i)
                cp16(dst + (uint32_t)(t + i * 256) * 16u, src + 4 * (t + i * 256));
            cp_commit();
        }

        const float* vb = v_sm + buf * 8192;
        float acc[4][2];
#pragma unroll
        for (int j = 0; j < 4; ++j) { acc[j][0] = 0.f; acc[j][1] = 0.f; }

#pragma unroll 4
        for (int d = 0; d < D; d += 4) {
            float2 w0 = *reinterpret_cast<const float2*>(&W_sm[(d + 0) * R + r]);
            float2 w1 = *reinterpret_cast<const float2*>(&W_sm[(d + 1) * R + r]);
            float2 w2 = *reinterpret_cast<const float2*>(&W_sm[(d + 2) * R + r]);
            float2 w3 = *reinterpret_cast<const float2*>(&W_sm[(d + 3) * R + r]);
#pragma unroll
            for (int j = 0; j < 4; ++j) {
                float4 v = *reinterpret_cast<const float4*>(&vb[(rg * 4 + j) * D + d]);
                acc[j][0] = fmaf(v.x, w0.x, acc[j][0]);
                acc[j][1] = fmaf(v.x, w0.y, acc[j][1]);
                acc[j][0] = fmaf(v.y, w1.x, acc[j][0]);
                acc[j][1] = fmaf(v.y, w1.y, acc[j][1]);
                acc[j][0] = fmaf(v.z, w2.x, acc[j][0]);
                acc[j][1] = fmaf(v.z, w2.y, acc[j][1]);
                acc[j][0] = fmaf(v.w, w3.x, acc[j][0]);
                acc[j][1] = fmaf(v.w, w3.y, acc[j][1]);
            }
        }

#pragma unroll
        for (int j = 0; j < 4; ++j) {
            const size_t base = (size_t)(row0 + bat * 32 + rg * 4 + j) * R;
            if (which) {
                out[base + kslot(r)]     = f2tf(acc[j][0]);
                out[base + kslot(r + 1)] = f2tf(acc[j][1]);
            } else {
                uint2 o = make_uint2(f2tf(acc[j][0]), f2tf(acc[j][1]));
                *reinterpret_cast<uint2*>(&out[base + r]) = o;
            }
        }
    }
}

// ---------------------------------------------------------------------------
// Kernel 1b: g_vt[b][d][m'] = tf32(val[b][m][d]), m' k-permuted in 8-groups
// ---------------------------------------------------------------------------
__global__ void __launch_bounds__(256) vt_kernel(const float* __restrict__ val) {
    __shared__ float tile[64 * 65];
    const int b = blockIdx.z, m0 = blockIdx.x * 64, d0 = blockIdx.y * 64;
    const int t = threadIdx.x;

#pragma unroll
    for (int it = 0; it < 4; ++it) {
        int p = t + it * 256;
        int row = p >> 4, c4 = p & 15;
        float4 v = *reinterpret_cast<const float4*>(
            val + ((size_t)b * N + m0 + row) * D + d0 + 4 * c4);
        tile[(4 * c4 + 0) * 65 + row] = v.x;
        tile[(4 * c4 + 1) * 65 + row] = v.y;
        tile[(4 * c4 + 2) * 65 + row] = v.z;
        tile[(4 * c4 + 3) * 65 + row] = v.w;
    }
    __syncthreads();

#pragma unroll
    for (int it = 0; it < 4; ++it) {
        int p = t + it * 256;
        int drow = p >> 4, mc4 = p & 15;
        uint4 o;
        uint32_t* op = reinterpret_cast<uint32_t*>(&o);
#pragma unroll
        for (int j = 0; j < 4; ++j) {
            int s = 4 * mc4 + j;
            int so = s & 7;
            int w = (so >> 1) + ((so & 1) << 2);
            op[j] = f2tf(tile[drow * 65 + (s & ~7) + w]);
        }
        *reinterpret_cast<uint4*>(
            &g_vt[((size_t)b * D + d0 + drow) * N + m0 + 4 * mc4]) = o;
    }
}

// ---------------------------------------------------------------------------
// Kernel 2: fused scores -> softsign -> (edges@state, edges@val), mma.sync.
// 16 warps; TN=32 double-buffered cp.async; Q fragments register-resident.
// ---------------------------------------------------------------------------
__global__ void __launch_bounds__(THREADS) prop_kernel(const float* __restrict__ state,
                                                       float* __restrict__ out_ds,
                                                       float* __restrict__ out_dv) {
    extern __shared__ float sm[];
    uint32_t* smU = reinterpret_cast<uint32_t*>(sm);
    const uint32_t sbase = smem_u32(sm);

    const int b  = blockIdx.y;
    const int n0 = blockIdx.x * TM;
    const int t  = threadIdx.x;
    const int wid = t >> 5, lane = t & 31;
    const int g = lane >> 2, tg = lane & 3;
    const int wr = wid & 3, wc = wid >> 2;        // row quarter / m-or-d group

    const int se = kslot(2 * tg);       // E-store slots for cols 2tg, 2tg+1
    const int so = kslot(2 * tg + 1);

    const uint32_t* gk_b  = g_k + (size_t)b * N * R;
    const uint32_t* gvt_b = g_vt + (size_t)b * D * N;
    const float* st_b = state + (size_t)b * N;

    auto prefetch = [&](int m0, int buf) {
        const int ofk  = buf ? OFK1 : OFK0;
        const int ofv  = buf ? OFV1 : OFV0;
        const int ofst = buf ? OFST1 : OFST0;
        {   // K tile: 32 rows x 16 uint4
            int row = t >> 4, c = t & 15;
            cp16(sbase + (uint32_t)(ofk + row * 72 + 4 * c) * 4u,
                 gk_b + (size_t)(m0 + row) * R + 4 * c);
        }
#pragma unroll
        for (int it = 0; it < 4; ++it) {   // VT: 256 rows x 8 uint4
            int p = t + it * THREADS;
            int row = p >> 3, c = p & 7;
            cp16(sbase + (uint32_t)(ofv + row * 40 + 4 * c) * 4u,
                 gvt_b + (size_t)row * N + m0 + 4 * c);
        }
        if (t < 8)
            cp16(sbase + (uint32_t)(ofst + 4 * t) * 4u, st_b + m0 + 4 * t);
    };

    prefetch(0, 0);
    cp_commit();

    // ---- Q A-fragments straight from global (one-time)
    uint32_t aq[8][4];
    {
        const uint32_t* q0 = g_q + ((size_t)b * N + n0 + 16 * wr + g) * R;
        const uint32_t* q1 = q0 + 8 * R;
#pragma unroll
        for (int ks = 0; ks < 8; ++ks) {
            aq[ks][0] = q0[8 * ks + tg];
            aq[ks][1] = q1[8 * ks + tg];
            aq[ks][2] = q0[8 * ks + tg + 4];
            aq[ks][3] = q1[8 * ks + tg + 4];
        }
    }

    float dv[8][4];
#pragma unroll
    for (int nt = 0; nt < 8; ++nt)
#pragma unroll
        for (int j = 0; j < 4; ++j) dv[nt][j] = 0.f;
    float ds0 = 0.f, ds1 = 0.f;

#pragma unroll 1
    for (int i = 0; i < N / TN; ++i) {
        const int buf = i & 1;
        const int ofk  = buf ? OFK1 : OFK0;
        const int ofv  = buf ? OFV1 : OFV0;
        const int ofst = buf ? OFST1 : OFST0;

        cp_wait0();
        __syncthreads();               // tile i resident; E + buf^1 free

        if (i + 1 < N / TN) {
            prefetch((i + 1) * TN, buf ^ 1);
            cp_commit();
        }

        // ---- MMA1: S(16x8 per warp) = Q . K^T
        float sacc[4] = {0.f, 0.f, 0.f, 0.f};
#pragma unroll
        for (int ks = 0; ks < 8; ++ks) {
            uint2 bb = *reinterpret_cast<const uint2*>(
                &sm[ofk + (8 * wc + g) * 72 + 8 * ks + 2 * tg]);
            mma_tf32(sacc, aq[ks], bb.x, bb.y);
        }

        // ---- softsign + delta_state + E(tf32, permuted slots)
        {
            const int c0 = 8 * wc + 2 * tg;
            float e00 = __fdividef(sacc[0], 1.f + fabsf(sacc[0]));
            float e01 = __fdividef(sacc[1], 1.f + fabsf(sacc[1]));
            float e10 = __fdividef(sacc[2], 1.f + fabsf(sacc[2]));
            float e11 = __fdividef(sacc[3], 1.f + fabsf(sacc[3]));
            float s0 = sm[ofst + c0], s1 = sm[ofst + c0 + 1];
            ds0 = fmaf(e00, s0, fmaf(e01, s1, ds0));
            ds1 = fmaf(e10, s0, fmaf(e11, s1, ds1));
            const int er0 = OFE + (16 * wr + g) * 40 + 8 * wc;
            const int er1 = er0 + 8 * 40;
            smU[er0 + se] = f2tf(e00);
            smU[er0 + so] = f2tf(e01);
            smU[er1 + se] = f2tf(e10);
            smU[er1 + so] = f2tf(e11);
        }
        __syncthreads();

        // ---- MMA2: DV(16x64 per warp) += E . V   (k = 32 -> 4 steps)
#pragma unroll
        for (int ks = 0; ks < 4; ++ks) {
            uint2 ae0 = *reinterpret_cast<const uint2*>(
                &sm[OFE + (16 * wr + g) * 40 + 8 * ks + 2 * tg]);
            uint2 ae1 = *reinterpret_cast<const uint2*>(
                &sm[OFE + (16 * wr + g + 8) * 40 + 8 * ks + 2 * tg]);
            uint32_t a[4] = {ae0.x, ae1.x, ae0.y, ae1.y};
#pragma unroll
            for (int nt = 0; nt < 8; ++nt) {
                uint2 bb = *reinterpret_cast<const uint2*>(
                    &sm[ofv + (64 * wc + 8 * nt + g) * 40 + 8 * ks + 2 * tg]);
                mma_tf32(dv[nt], a, bb.x, bb.y);
            }
        }
    }

    // ---- epilogue: DV writes
    {
        const int rowA = n0 + 16 * wr + g;
        float* dA = out_dv + ((size_t)b * N + rowA) * D;
        float* dB = dA + 8 * D;
#pragma unroll
        for (int nt = 0; nt < 8; ++nt) {
            const int col = 64 * wc + 8 * nt + 2 * tg;
            *reinterpret_cast<float2*>(dA + col) = make_float2(dv[nt][0], dv[nt][1]);
            *reinterpret_cast<float2*>(dB + col) = make_float2(dv[nt][2], dv[nt][3]);
        }
    }

    // ---- delta_state reduction: quad-reduce, then 4 wc-partials per row
    ds0 += __shfl_xor_sync(0xFFFFFFFF, ds0, 1);
    ds0 += __shfl_xor_sync(0xFFFFFFFF, ds0, 2);
    ds1 += __shfl_xor_sync(0xFFFFFFFF, ds1, 1);
    ds1 += __shfl_xor_sync(0xFFFFFFFF, ds1, 2);
    __syncthreads();
    if (tg == 0) {
        sm[OFRD + (16 * wr + g) * 4 + wc]     = ds0;
        sm[OFRD + (16 * wr + g + 8) * 4 + wc] = ds1;
    }
    __syncthreads();
    if (t < TM)
        out_ds[b * N + n0 + t] = (sm[OFRD + t * 4] + sm[OFRD + t * 4 + 1]) +
                                 (sm[OFRD + t * 4 + 2] + sm[OFRD + t * 4 + 3]);
}

}  // namespace

extern "C" void kernel_launch(void* const* d_in, const int* in_sizes, int n_in,
                              void* d_out, int out_size) {
    const float* state = (const float*)d_in[0];   // [B, N]
    const float* val   = (const float*)d_in[1];   // [B, N, D]
    const float* Wq    = (const float*)d_in[2];   // [D, R]
    const float* Wk    = (const float*)d_in[3];   // [D, R]

    float* out_ds = (float*)d_out;                // [B, N]
    float* out_dv = out_ds + B * N;               // [B, N, D]

    constexpr int QK_SMEM = (D * R + 2 * 32 * D) * 4;   // 128KB
    cudaFuncSetAttribute(qk_kernel, cudaFuncAttributeMaxDynamicSharedMemorySize, QK_SMEM);
    cudaFuncSetAttribute(prop_kernel, cudaFuncAttributeMaxDynamicSharedMemorySize, SMEM_BYTES);

    qk_kernel<<<(B * N / 128) * 2, 256, QK_SMEM>>>(val, Wq, Wk);
    vt_kernel<<<dim3(N / 64, D / 64, B), 256>>>(val);
    prop_kernel<<<dim3(N / TM, B), THREADS, SMEM_BYTES>>>(state, out_ds, out_dv);
}

// round 7
// speedup vs baseline: 6.4270x; 1.5550x over previous
#include <cuda_runtime.h>
#include <cuda_fp16.h>
#include <cstdint>

namespace {

constexpr int B = 2, N = 4096, D = 256, R = 64;
constexpr int TM = 64;         // n-rows per block
constexpr int TN = 32;         // m-tile
constexpr int THREADS = 512;   // 16 warps

// prop smem layout in uint32 units. Strides: K=40, VT/E=24 (mod 32 = 8 / 24:
// conflict-free for 8-row x uint2 fragment phases).
constexpr int OFE   = 0;                     // 64 x 24
constexpr int OFK0  = OFE + 64 * 24;         // 32 x 40
constexpr int OFK1  = OFK0 + 32 * 40;
constexpr int OFV0  = OFK1 + 32 * 40;        // 256 x 24
constexpr int OFV1  = OFV0 + 256 * 24;
constexpr int OFST0 = OFV1 + 256 * 24;       // 32 (floats)
constexpr int OFST1 = OFST0 + 32;
constexpr int OFRD  = OFST1 + 32;            // 256 (floats)
constexpr int SMEM_U32 = OFRD + 256;
constexpr int SMEM_BYTES = SMEM_U32 * 4;     // ~66.8 KB

// fp16 pair-packed globals (uint32 = half2 = 2 adjacent k/m entries)
__device__ uint32_t g_q[B * N * (R / 2)];      // pair-slot permuted
__device__ uint32_t g_k[B * N * (R / 2)];      // pair-slot permuted
__device__ uint32_t g_vt[B * D * (N / 2)];     // [b][d][m-pair], permuted

// per-8-pair-group slot permutation: pair l -> slot (l&3)*2 + (l>>2)
__host__ __device__ __forceinline__ int kslot(int p) {
    return (p & ~7) | (((p & 3) << 1) | ((p & 7) >> 2));
}

__device__ __forceinline__ uint32_t pack_h2(float lo, float hi) {
    __half2 h = __floats2half2_rn(lo, hi);
    return *reinterpret_cast<uint32_t*>(&h);
}

__device__ __forceinline__ uint32_t smem_u32p(const void* p) {
    uint32_t a;
    asm("{ .reg .u64 t; cvta.to.shared.u64 t, %1; cvt.u32.u64 %0, t; }" : "=r"(a) : "l"(p));
    return a;
}

__device__ __forceinline__ void cp16(uint32_t dst, const void* src) {
    asm volatile("cp.async.cg.shared.global [%0], [%1], 16;" :: "r"(dst), "l"(src));
}
__device__ __forceinline__ void cp_commit() { asm volatile("cp.async.commit_group;"); }
__device__ __forceinline__ void cp_wait0()  { asm volatile("cp.async.wait_group 0;"); }

// m16n8k16 f16 MMA, f32 accumulate
__device__ __forceinline__ void mma_f16(float (&d)[4], const uint32_t (&a)[4],
                                        uint32_t b0, uint32_t b1) {
    asm volatile(
        "mma.sync.aligned.m16n8k16.row.col.f32.f16.f16.f32 "
        "{%0,%1,%2,%3}, {%4,%5,%6,%7}, {%8,%9}, {%0,%1,%2,%3};"
        : "+f"(d[0]), "+f"(d[1]), "+f"(d[2]), "+f"(d[3])
        : "r"(a[0]), "r"(a[1]), "r"(a[2]), "r"(a[3]), "r"(b0), "r"(b1));
}

// ---------------------------------------------------------------------------
// Kernel 1: q = val@Wq, k = val@Wk -> fp16 pairs, pair-slot permuted.
// 128 rows/block, W staged once, v batches double-buffered.
// ---------------------------------------------------------------------------
__global__ void __launch_bounds__(256) qk_kernel(const float* __restrict__ val,
                                                 const float* __restrict__ Wq,
                                                 const float* __restrict__ Wk) {
    extern __shared__ float qsm[];
    float* W_sm = qsm;                   // D*R
    float* v_sm = qsm + D * R;           // 2 x 32*D
    const uint32_t vbase = smem_u32p(qsm) + D * R * 4;

    const int t = threadIdx.x;
    const int which = blockIdx.x & 1;
    const int row0 = (blockIdx.x >> 1) * 128;

    const float* __restrict__ W = which ? Wk : Wq;
    uint32_t* __restrict__ out = which ? g_k : g_q;

    {
        const float* src = val + (size_t)row0 * D;
#pragma unroll
        for (int i = 0; i < 8; ++i)
            cp16(vbase + (uint32_t)(t + i * 256) * 16u, src + 4 * (t + i * 256));
        cp_commit();
    }
    {
        const float4* wsrc = reinterpret_cast<const float4*>(W);
        float4* wdst = reinterpret_cast<float4*>(W_sm);
#pragma unroll
        for (int i = 0; i < 16; ++i)
            wdst[t + i * 256] = wsrc[t + i * 256];
    }

    const int c  = t & 31;             // pair index (cols 2c, 2c+1)
    const int rg = t >> 5;
    const int slot = kslot(c);

#pragma unroll 1
    for (int bat = 0; bat < 4; ++bat) {
        const int buf = bat & 1;
        cp_wait0();
        __syncthreads();

        if (bat + 1 < 4) {
            const float* src = val + (size_t)(row0 + (bat + 1) * 32) * D;
            const uint32_t dst = vbase + (uint32_t)(buf ^ 1) * 32768u;
#pragma unroll
            for (int i = 0; i < 8; ++i)
                cp16(dst + (uint32_t)(t + i * 256) * 16u, src + 4 * (t + i * 256));
            cp_commit();
        }

        const float* vb = v_sm + buf * 8192;
        float acc[4][2];
#pragma unroll
        for (int j = 0; j < 4; ++j) { acc[j][0] = 0.f; acc[j][1] = 0.f; }

#pragma unroll 4
        for (int d = 0; d < D; d += 4) {
            float2 w0 = *reinterpret_cast<const float2*>(&W_sm[(d + 0) * R + 2 * c]);
            float2 w1 = *reinterpret_cast<const float2*>(&W_sm[(d + 1) * R + 2 * c]);
            float2 w2 = *reinterpret_cast<const float2*>(&W_sm[(d + 2) * R + 2 * c]);
            float2 w3 = *reinterpret_cast<const float2*>(&W_sm[(d + 3) * R + 2 * c]);
#pragma unroll
            for (int j = 0; j < 4; ++j) {
                float4 v = *reinterpret_cast<const float4*>(&vb[(rg * 4 + j) * D + d]);
                acc[j][0] = fmaf(v.x, w0.x, acc[j][0]);
                acc[j][1] = fmaf(v.x, w0.y, acc[j][1]);
                acc[j][0] = fmaf(v.y, w1.x, acc[j][0]);
                acc[j][1] = fmaf(v.y, w1.y, acc[j][1]);
                acc[j][0] = fmaf(v.z, w2.x, acc[j][0]);
                acc[j][1] = fmaf(v.z, w2.y, acc[j][1]);
                acc[j][0] = fmaf(v.w, w3.x, acc[j][0]);
                acc[j][1] = fmaf(v.w, w3.y, acc[j][1]);
            }
        }

#pragma unroll
        for (int j = 0; j < 4; ++j)
            out[(size_t)(row0 + bat * 32 + rg * 4 + j) * 32 + slot] =
                pack_h2(acc[j][0], acc[j][1]);
    }
}

// ---------------------------------------------------------------------------
// Kernel 1b: g_vt[b][d][m-pair slot] = half2(val[m], val[m+1]), permuted.
// ---------------------------------------------------------------------------
__global__ void __launch_bounds__(256) vt_kernel(const float* __restrict__ val) {
    __shared__ float tile[64 * 65];
    const int b = blockIdx.z, m0 = blockIdx.x * 64, d0 = blockIdx.y * 64;
    const int t = threadIdx.x;

#pragma unroll
    for (int it = 0; it < 4; ++it) {
        int p = t + it * 256;
        int row = p >> 4, c4 = p & 15;
        float4 v = *reinterpret_cast<const float4*>(
            val + ((size_t)b * N + m0 + row) * D + d0 + 4 * c4);
        tile[(4 * c4 + 0) * 65 + row] = v.x;
        tile[(4 * c4 + 1) * 65 + row] = v.y;
        tile[(4 * c4 + 2) * 65 + row] = v.z;
        tile[(4 * c4 + 3) * 65 + row] = v.w;
    }
    __syncthreads();

    // 64 d-rows x 16 uint2 outputs (32 slots). slot 2jj <- pair jj, slot 2jj+1 <- pair jj+4.
#pragma unroll
    for (int it = 0; it < 4; ++it) {
        int p = t + it * 256;
        int drow = p >> 4, j = p & 15;
        int grp = j >> 2, jj = j & 3;
        int mb = grp * 16;
        const float* tr = &tile[drow * 65];
        uint2 o;
        o.x = pack_h2(tr[mb + 2 * jj],     tr[mb + 2 * jj + 1]);
        o.y = pack_h2(tr[mb + 2 * jj + 8], tr[mb + 2 * jj + 9]);
        *reinterpret_cast<uint2*>(
            &g_vt[((size_t)b * D + d0 + drow) * (N / 2) + m0 / 2 + 2 * j]) = o;
    }
}

// ---------------------------------------------------------------------------
// Kernel 2: fused scores -> softsign -> (edges@state, edges@val), fp16 MMA.
// ---------------------------------------------------------------------------
__global__ void __launch_bounds__(THREADS) prop_kernel(const float* __restrict__ state,
                                                       float* __restrict__ out_ds,
                                                       float* __restrict__ out_dv) {
    extern __shared__ float smf[];
    uint32_t* sm = reinterpret_cast<uint32_t*>(smf);
    const uint32_t sbase = smem_u32p(smf);

    const int b  = blockIdx.y;
    const int n0 = blockIdx.x * TM;
    const int t  = threadIdx.x;
    const int wid = t >> 5, lane = t & 31;
    const int g = lane >> 2, tg = lane & 3;
    const int wr = wid & 3, wc = wid >> 2;

    const uint32_t* gk_b  = g_k + (size_t)b * N * 32;
    const uint32_t* gvt_b = g_vt + (size_t)b * D * (N / 2);
    const float* st_b = state + (size_t)b * N;

    auto prefetch = [&](int m0, int buf) {
        const int ofk  = buf ? OFK1 : OFK0;
        const int ofv  = buf ? OFV1 : OFV0;
        const int ofst = buf ? OFST1 : OFST0;
        if (t < 256) {   // K tile: 32 rows x 8 uint4
            int row = t >> 3, c = t & 7;
            cp16(sbase + (uint32_t)(ofk + row * 40 + 4 * c) * 4u,
                 gk_b + (size_t)(m0 + row) * 32 + 4 * c);
        }
#pragma unroll
        for (int it = 0; it < 2; ++it) {   // VT: 256 rows x 4 uint4
            int p = t + it * THREADS;
            int row = p >> 2, c = p & 3;
            cp16(sbase + (uint32_t)(ofv + row * 24 + 4 * c) * 4u,
                 gvt_b + (size_t)row * (N / 2) + m0 / 2 + 4 * c);
        }
        if (t < 8)
            cp16(sbase + (uint32_t)(ofst + 4 * t) * 4u, st_b + m0 + 4 * t);
    };

    prefetch(0, 0);
    cp_commit();

    // ---- Q A-fragments from permuted global (one-time): 4 k16-steps
    uint32_t aq[4][4];
    {
        const uint32_t* q0 = g_q + ((size_t)b * N + n0 + 16 * wr + g) * 32;
        const uint32_t* q1 = q0 + 8 * 32;
#pragma unroll
        for (int ks = 0; ks < 4; ++ks) {
            uint2 u0 = *reinterpret_cast<const uint2*>(&q0[8 * ks + 2 * tg]);
            uint2 u1 = *reinterpret_cast<const uint2*>(&q1[8 * ks + 2 * tg]);
            aq[ks][0] = u0.x; aq[ks][1] = u1.x; aq[ks][2] = u0.y; aq[ks][3] = u1.y;
        }
    }

    // E store slot (pair p = 4wc+tg)
    const int ep = 4 * wc + tg;
    const int eslot = kslot(ep);

    float dv[8][4];
#pragma unroll
    for (int nt = 0; nt < 8; ++nt)
#pragma unroll
        for (int j = 0; j < 4; ++j) dv[nt][j] = 0.f;
    float ds0 = 0.f, ds1 = 0.f;

#pragma unroll 1
    for (int i = 0; i < N / TN; ++i) {
        const int buf = i & 1;
        const int ofk  = buf ? OFK1 : OFK0;
        const int ofv  = buf ? OFV1 : OFV0;
        const int ofst = buf ? OFST1 : OFST0;

        cp_wait0();
        __syncthreads();

        if (i + 1 < N / TN) {
            prefetch((i + 1) * TN, buf ^ 1);
            cp_commit();
        }

        // ---- MMA1: S(16x8 per warp) = Q . K^T  (R=64 -> 4 k16 steps)
        float sacc[4] = {0.f, 0.f, 0.f, 0.f};
#pragma unroll
        for (int ks = 0; ks < 4; ++ks) {
            uint2 bb = *reinterpret_cast<const uint2*>(
                &sm[ofk + (8 * wc + g) * 40 + 8 * ks + 2 * tg]);
            mma_f16(sacc, aq[ks], bb.x, bb.y);
        }

        // ---- softsign + delta_state + E(fp16 pairs, permuted slots)
        {
            const int c0 = 8 * wc + 2 * tg;
            float e00 = __fdividef(sacc[0], 1.f + fabsf(sacc[0]));
            float e01 = __fdividef(sacc[1], 1.f + fabsf(sacc[1]));
            float e10 = __fdividef(sacc[2], 1.f + fabsf(sacc[2]));
            float e11 = __fdividef(sacc[3], 1.f + fabsf(sacc[3]));
            float s0 = smf[ofst + c0], s1 = smf[ofst + c0 + 1];
            ds0 = fmaf(e00, s0, fmaf(e01, s1, ds0));
            ds1 = fmaf(e10, s0, fmaf(e11, s1, ds1));
            sm[OFE + (16 * wr + g) * 24 + eslot]     = pack_h2(e00, e01);
            sm[OFE + (16 * wr + g + 8) * 24 + eslot] = pack_h2(e10, e11);
        }
        __syncthreads();

        // ---- MMA2: DV(16x64 per warp) += E . V  (k=32 -> 2 k16 steps)
#pragma unroll
        for (int ks = 0; ks < 2; ++ks) {
            uint2 A0 = *reinterpret_cast<const uint2*>(
                &sm[OFE + (16 * wr + g) * 24 + 8 * ks + 2 * tg]);
            uint2 A1 = *reinterpret_cast<const uint2*>(
                &sm[OFE + (16 * wr + g + 8) * 24 + 8 * ks + 2 * tg]);
            uint32_t a[4] = {A0.x, A1.x, A0.y, A1.y};
#pragma unroll
            for (int nt = 0; nt < 8; ++nt) {
                uint2 bb = *reinterpret_cast<const uint2*>(
                    &sm[ofv + (64 * wc + 8 * nt + g) * 24 + 8 * ks + 2 * tg]);
                mma_f16(dv[nt], a, bb.x, bb.y);
            }
        }
    }

    // ---- epilogue: DV writes
    {
        const int rowA = n0 + 16 * wr + g;
        float* dA = out_dv + ((size_t)b * N + rowA) * D;
        float* dB = dA + 8 * D;
#pragma unroll
        for (int nt = 0; nt < 8; ++nt) {
            const int col = 64 * wc + 8 * nt + 2 * tg;
            *reinterpret_cast<float2*>(dA + col) = make_float2(dv[nt][0], dv[nt][1]);
            *reinterpret_cast<float2*>(dB + col) = make_float2(dv[nt][2], dv[nt][3]);
        }
    }

    // ---- delta_state reduction
    ds0 += __shfl_xor_sync(0xFFFFFFFF, ds0, 1);
    ds0 += __shfl_xor_sync(0xFFFFFFFF, ds0, 2);
    ds1 += __shfl_xor_sync(0xFFFFFFFF, ds1, 1);
    ds1 += __shfl_xor_sync(0xFFFFFFFF, ds1, 2);
    __syncthreads();
    if (tg == 0) {
        smf[OFRD + (16 * wr + g) * 4 + wc]     = ds0;
        smf[OFRD + (16 * wr + g + 8) * 4 + wc] = ds1;
    }
    __syncthreads();
    if (t < TM)
        out_ds[b * N + n0 + t] = (smf[OFRD + t * 4] + smf[OFRD + t * 4 + 1]) +
                                 (smf[OFRD + t * 4 + 2] + smf[OFRD + t * 4 + 3]);
}

}  // namespace

extern "C" void kernel_launch(void* const* d_in, const int* in_sizes, int n_in,
                              void* d_out, int out_size) {
    const float* state = (const float*)d_in[0];   // [B, N]
    const float* val   = (const float*)d_in[1];   // [B, N, D]
    const float* Wq    = (const float*)d_in[2];   // [D, R]
    const float* Wk    = (const float*)d_in[3];   // [D, R]

    float* out_ds = (float*)d_out;                // [B, N]
    float* out_dv = out_ds + B * N;               // [B, N, D]

    constexpr int QK_SMEM = (D * R + 2 * 32 * D) * 4;   // 128KB
    cudaFuncSetAttribute(qk_kernel, cudaFuncAttributeMaxDynamicSharedMemorySize, QK_SMEM);
    cudaFuncSetAttribute(prop_kernel, cudaFuncAttributeMaxDynamicSharedMemorySize, SMEM_BYTES);

    qk_kernel<<<(B * N / 128) * 2, 256, QK_SMEM>>>(val, Wq, Wk);
    vt_kernel<<<dim3(N / 64, D / 64, B), 256>>>(val);
    prop_kernel<<<dim3(N / TM, B), THREADS, SMEM_BYTES>>>(state, out_ds, out_dv);
}

// round 8
// speedup vs baseline: 7.1996x; 1.1202x over previous
#include <cuda_runtime.h>
#include <cuda_fp16.h>
#include <cstdint>

namespace {

constexpr int B = 2, N = 4096, D = 256, R = 64;
constexpr int TM = 64;         // n-rows per block
constexpr int TN = 64;         // m-tile
constexpr int THREADS = 512;   // 16 warps

// prop smem layout in uint32 units; stride 40 (mod 32 == 8) is conflict-free
// for all 8-row x uint2 fragment phase patterns used below.
constexpr int OFE   = 0;                     // 64 x 40 (32 pair-cols used)
constexpr int OFK0  = OFE + 64 * 40;         // 64 x 40
constexpr int OFK1  = OFK0 + 64 * 40;
constexpr int OFV0  = OFK1 + 64 * 40;        // 256 x 40
constexpr int OFV1  = OFV0 + 256 * 40;
constexpr int OFST0 = OFV1 + 256 * 40;       // 64 (floats)
constexpr int OFST1 = OFST0 + 64;
constexpr int OFRD  = OFST1 + 64;            // 256 (floats)
constexpr int SMEM_U32 = OFRD + 256;
constexpr int SMEM_BYTES = SMEM_U32 * 4;     // ~111.6 KB -> 1 block/SM

// fp16 pair-packed globals (uint32 = half2 = 2 adjacent k/m entries)
__device__ uint32_t g_q[B * N * (R / 2)];      // pair-slot permuted
__device__ uint32_t g_k[B * N * (R / 2)];      // pair-slot permuted
__device__ uint32_t g_vt[B * D * (N / 2)];     // [b][d][m-pair], permuted

// per-8-pair-group slot permutation: pair l -> slot (l&3)*2 + (l>>2)
__host__ __device__ __forceinline__ int kslot(int p) {
    return (p & ~7) | (((p & 3) << 1) | ((p & 7) >> 2));
}

__device__ __forceinline__ uint32_t pack_h2(float lo, float hi) {
    __half2 h = __floats2half2_rn(lo, hi);
    return *reinterpret_cast<uint32_t*>(&h);
}

__device__ __forceinline__ uint32_t smem_u32p(const void* p) {
    uint32_t a;
    asm("{ .reg .u64 t; cvta.to.shared.u64 t, %1; cvt.u32.u64 %0, t; }" : "=r"(a) : "l"(p));
    return a;
}

__device__ __forceinline__ void cp16(uint32_t dst, const void* src) {
    asm volatile("cp.async.cg.shared.global [%0], [%1], 16;" :: "r"(dst), "l"(src));
}
__device__ __forceinline__ void cp_commit() { asm volatile("cp.async.commit_group;"); }
__device__ __forceinline__ void cp_wait0()  { asm volatile("cp.async.wait_group 0;"); }

// m16n8k16 f16 MMA, f32 accumulate
__device__ __forceinline__ void mma_f16(float (&d)[4], const uint32_t (&a)[4],
                                        uint32_t b0, uint32_t b1) {
    asm volatile(
        "mma.sync.aligned.m16n8k16.row.col.f32.f16.f16.f32 "
        "{%0,%1,%2,%3}, {%4,%5,%6,%7}, {%8,%9}, {%0,%1,%2,%3};"
        : "+f"(d[0]), "+f"(d[1]), "+f"(d[2]), "+f"(d[3])
        : "r"(a[0]), "r"(a[1]), "r"(a[2]), "r"(a[3]), "r"(b0), "r"(b1));
}

// ---------------------------------------------------------------------------
// Kernel 1: q = val@Wq, k = val@Wk -> fp16 pairs, pair-slot permuted.
// (unchanged from round 7)
// ---------------------------------------------------------------------------
__global__ void __launch_bounds__(256) qk_kernel(const float* __restrict__ val,
                                                 const float* __restrict__ Wq,
                                                 const float* __restrict__ Wk) {
    extern __shared__ float qsm[];
    float* W_sm = qsm;                   // D*R
    float* v_sm = qsm + D * R;           // 2 x 32*D
    const uint32_t vbase = smem_u32p(qsm) + D * R * 4;

    const int t = threadIdx.x;
    const int which = blockIdx.x & 1;
    const int row0 = (blockIdx.x >> 1) * 128;

    const float* __restrict__ W = which ? Wk : Wq;
    uint32_t* __restrict__ out = which ? g_k : g_q;

    {
        const float* src = val + (size_t)row0 * D;
#pragma unroll
        for (int i = 0; i < 8; ++i)
            cp16(vbase + (uint32_t)(t + i * 256) * 16u, src + 4 * (t + i * 256));
        cp_commit();
    }
    {
        const float4* wsrc = reinterpret_cast<const float4*>(W);
        float4* wdst = reinterpret_cast<float4*>(W_sm);
#pragma unroll
        for (int i = 0; i < 16; ++i)
            wdst[t + i * 256] = wsrc[t + i * 256];
    }

    const int c  = t & 31;             // pair index (cols 2c, 2c+1)
    const int rg = t >> 5;
    const int slot = kslot(c);

#pragma unroll 1
    for (int bat = 0; bat < 4; ++bat) {
        const int buf = bat & 1;
        cp_wait0();
        __syncthreads();

        if (bat + 1 < 4) {
            const float* src = val + (size_t)(row0 + (bat + 1) * 32) * D;
            const uint32_t dst = vbase + (uint32_t)(buf ^ 1) * 32768u;
#pragma unroll
            for (int i = 0; i < 8; ++i)
                cp16(dst + (uint32_t)(t + i * 256) * 16u, src + 4 * (t + i * 256));
            cp_commit();
        }

        const float* vb = v_sm + buf * 8192;
        float acc[4][2];
#pragma unroll
        for (int j = 0; j < 4; ++j) { acc[j][0] = 0.f; acc[j][1] = 0.f; }

#pragma unroll 4
        for (int d = 0; d < D; d += 4) {
            float2 w0 = *reinterpret_cast<const float2*>(&W_sm[(d + 0) * R + 2 * c]);
            float2 w1 = *reinterpret_cast<const float2*>(&W_sm[(d + 1) * R + 2 * c]);
            float2 w2 = *reinterpret_cast<const float2*>(&W_sm[(d + 2) * R + 2 * c]);
            float2 w3 = *reinterpret_cast<const float2*>(&W_sm[(d + 3) * R + 2 * c]);
#pragma unroll
            for (int j = 0; j < 4; ++j) {
                float4 v = *reinterpret_cast<const float4*>(&vb[(rg * 4 + j) * D + d]);
                acc[j][0] = fmaf(v.x, w0.x, acc[j][0]);
                acc[j][1] = fmaf(v.x, w0.y, acc[j][1]);
                acc[j][0] = fmaf(v.y, w1.x, acc[j][0]);
                acc[j][1] = fmaf(v.y, w1.y, acc[j][1]);
                acc[j][0] = fmaf(v.z, w2.x, acc[j][0]);
                acc[j][1] = fmaf(v.z, w2.y, acc[j][1]);
                acc[j][0] = fmaf(v.w, w3.x, acc[j][0]);
                acc[j][1] = fmaf(v.w, w3.y, acc[j][1]);
            }
        }

#pragma unroll
        for (int j = 0; j < 4; ++j)
            out[(size_t)(row0 + bat * 32 + rg * 4 + j) * 32 + slot] =
                pack_h2(acc[j][0], acc[j][1]);
    }
}

// ---------------------------------------------------------------------------
// Kernel 1b: g_vt[b][d][m-pair slot] = half2(val[m], val[m+1]), permuted.
// (unchanged from round 7)
// ---------------------------------------------------------------------------
__global__ void __launch_bounds__(256) vt_kernel(const float* __restrict__ val) {
    __shared__ float tile[64 * 65];
    const int b = blockIdx.z, m0 = blockIdx.x * 64, d0 = blockIdx.y * 64;
    const int t = threadIdx.x;

#pragma unroll
    for (int it = 0; it < 4; ++it) {
        int p = t + it * 256;
        int row = p >> 4, c4 = p & 15;
        float4 v = *reinterpret_cast<const float4*>(
            val + ((size_t)b * N + m0 + row) * D + d0 + 4 * c4);
        tile[(4 * c4 + 0) * 65 + row] = v.x;
        tile[(4 * c4 + 1) * 65 + row] = v.y;
        tile[(4 * c4 + 2) * 65 + row] = v.z;
        tile[(4 * c4 + 3) * 65 + row] = v.w;
    }
    __syncthreads();

#pragma unroll
    for (int it = 0; it < 4; ++it) {
        int p = t + it * 256;
        int drow = p >> 4, j = p & 15;
        int grp = j >> 2, jj = j & 3;
        int mb = grp * 16;
        const float* tr = &tile[drow * 65];
        uint2 o;
        o.x = pack_h2(tr[mb + 2 * jj],     tr[mb + 2 * jj + 1]);
        o.y = pack_h2(tr[mb + 2 * jj + 8], tr[mb + 2 * jj + 9]);
        *reinterpret_cast<uint2*>(
            &g_vt[((size_t)b * D + d0 + drow) * (N / 2) + m0 / 2 + 2 * j]) = o;
    }
}

// ---------------------------------------------------------------------------
// Kernel 2: fused scores -> softsign -> (edges@state, edges@val), fp16 MMA.
// TN=64 m-tiles: 64 tiles, 2 barriers each. MMA1 warp tile 16x16.
// ---------------------------------------------------------------------------
__global__ void __launch_bounds__(THREADS) prop_kernel(const float* __restrict__ state,
                                                       float* __restrict__ out_ds,
                                                       float* __restrict__ out_dv) {
    extern __shared__ float smf[];
    uint32_t* sm = reinterpret_cast<uint32_t*>(smf);
    const uint32_t sbase = smem_u32p(smf);

    const int b  = blockIdx.y;
    const int n0 = blockIdx.x * TM;
    const int t  = threadIdx.x;
    const int wid = t >> 5, lane = t & 31;
    const int g = lane >> 2, tg = lane & 3;
    const int wr = wid & 3, wc = wid >> 2;

    const uint32_t* gk_b  = g_k + (size_t)b * N * 32;
    const uint32_t* gvt_b = g_vt + (size_t)b * D * (N / 2);
    const float* st_b = state + (size_t)b * N;

    auto prefetch = [&](int m0, int buf) {
        const int ofk  = buf ? OFK1 : OFK0;
        const int ofv  = buf ? OFV1 : OFV0;
        const int ofst = buf ? OFST1 : OFST0;
        {   // K tile: 64 rows x 8 uint4
            int row = t >> 3, c = t & 7;
            cp16(sbase + (uint32_t)(ofk + row * 40 + 4 * c) * 4u,
                 gk_b + (size_t)(m0 + row) * 32 + 4 * c);
        }
#pragma unroll
        for (int it = 0; it < 4; ++it) {   // VT: 256 rows x 8 uint4
            int p = t + it * THREADS;
            int row = p >> 3, c = p & 7;
            cp16(sbase + (uint32_t)(ofv + row * 40 + 4 * c) * 4u,
                 gvt_b + (size_t)row * (N / 2) + m0 / 2 + 4 * c);
        }
        if (t < 16)
            cp16(sbase + (uint32_t)(ofst + 4 * t) * 4u, st_b + m0 + 4 * t);
    };

    prefetch(0, 0);
    cp_commit();

    // ---- Q A-fragments from permuted global (one-time): 4 k16-steps
    uint32_t aq[4][4];
    {
        const uint32_t* q0 = g_q + ((size_t)b * N + n0 + 16 * wr + g) * 32;
        const uint32_t* q1 = q0 + 8 * 32;
#pragma unroll
        for (int ks = 0; ks < 4; ++ks) {
            uint2 u0 = *reinterpret_cast<const uint2*>(&q0[8 * ks + 2 * tg]);
            uint2 u1 = *reinterpret_cast<const uint2*>(&q1[8 * ks + 2 * tg]);
            aq[ks][0] = u0.x; aq[ks][1] = u1.x; aq[ks][2] = u0.y; aq[ks][3] = u1.y;
        }
    }

    // E store slots for MMA1 n8 tiles nt=0,1: pair p = 8wc + 4nt + tg
    const int eslot0 = kslot(8 * wc + tg);
    const int eslot1 = kslot(8 * wc + 4 + tg);

    float dv[8][4];
#pragma unroll
    for (int nt = 0; nt < 8; ++nt)
#pragma unroll
        for (int j = 0; j < 4; ++j) dv[nt][j] = 0.f;
    float ds0 = 0.f, ds1 = 0.f;

#pragma unroll 1
    for (int i = 0; i < N / TN; ++i) {
        const int buf = i & 1;
        const int ofk  = buf ? OFK1 : OFK0;
        const int ofv  = buf ? OFV1 : OFV0;
        const int ofst = buf ? OFST1 : OFST0;

        cp_wait0();
        __syncthreads();

        if (i + 1 < N / TN) {
            prefetch((i + 1) * TN, buf ^ 1);
            cp_commit();
        }

        // ---- MMA1: S(16x16 per warp) = Q . K^T  (R=64 -> 4 k16 steps, 2 n8)
        float sacc[2][4];
#pragma unroll
        for (int nt = 0; nt < 2; ++nt)
#pragma unroll
            for (int j = 0; j < 4; ++j) sacc[nt][j] = 0.f;

#pragma unroll
        for (int ks = 0; ks < 4; ++ks) {
#pragma unroll
            for (int nt = 0; nt < 2; ++nt) {
                uint2 bb = *reinterpret_cast<const uint2*>(
                    &sm[ofk + (16 * wc + 8 * nt + g) * 40 + 8 * ks + 2 * tg]);
                mma_f16(sacc[nt], aq[ks], bb.x, bb.y);
            }
        }

        // ---- softsign + delta_state + E(fp16 pairs, permuted slots)
#pragma unroll
        for (int nt = 0; nt < 2; ++nt) {
            const int c0 = 16 * wc + 8 * nt + 2 * tg;
            float e00 = __fdividef(sacc[nt][0], 1.f + fabsf(sacc[nt][0]));
            float e01 = __fdividef(sacc[nt][1], 1.f + fabsf(sacc[nt][1]));
            float e10 = __fdividef(sacc[nt][2], 1.f + fabsf(sacc[nt][2]));
            float e11 = __fdividef(sacc[nt][3], 1.f + fabsf(sacc[nt][3]));
            float s0 = smf[ofst + c0], s1 = smf[ofst + c0 + 1];
            ds0 = fmaf(e00, s0, fmaf(e01, s1, ds0));
            ds1 = fmaf(e10, s0, fmaf(e11, s1, ds1));
            const int es = nt ? eslot1 : eslot0;
            sm[OFE + (16 * wr + g) * 40 + es]     = pack_h2(e00, e01);
            sm[OFE + (16 * wr + g + 8) * 40 + es] = pack_h2(e10, e11);
        }
        __syncthreads();

        // ---- MMA2: DV(16x64 per warp) += E . V  (k=64 -> 4 k16 steps)
#pragma unroll
        for (int ks = 0; ks < 4; ++ks) {
            uint2 A0 = *reinterpret_cast<const uint2*>(
                &sm[OFE + (16 * wr + g) * 40 + 8 * ks + 2 * tg]);
            uint2 A1 = *reinterpret_cast<const uint2*>(
                &sm[OFE + (16 * wr + g + 8) * 40 + 8 * ks + 2 * tg]);
            uint32_t a[4] = {A0.x, A1.x, A0.y, A1.y};
#pragma unroll
            for (int nt = 0; nt < 8; ++nt) {
                uint2 bb = *reinterpret_cast<const uint2*>(
                    &sm[ofv + (64 * wc + 8 * nt + g) * 40 + 8 * ks + 2 * tg]);
                mma_f16(dv[nt], a, bb.x, bb.y);
            }
        }
    }

    // ---- epilogue: DV writes
    {
        const int rowA = n0 + 16 * wr + g;
        float* dA = out_dv + ((size_t)b * N + rowA) * D;
        float* dB = dA + 8 * D;
#pragma unroll
        for (int nt = 0; nt < 8; ++nt) {
            const int col = 64 * wc + 8 * nt + 2 * tg;
            *reinterpret_cast<float2*>(dA + col) = make_float2(dv[nt][0], dv[nt][1]);
            *reinterpret_cast<float2*>(dB + col) = make_float2(dv[nt][2], dv[nt][3]);
        }
    }

    // ---- delta_state reduction (quad shuffle, then 4 wc-partials per row)
    ds0 += __shfl_xor_sync(0xFFFFFFFF, ds0, 1);
    ds0 += __shfl_xor_sync(0xFFFFFFFF, ds0, 2);
    ds1 += __shfl_xor_sync(0xFFFFFFFF, ds1, 1);
    ds1 += __shfl_xor_sync(0xFFFFFFFF, ds1, 2);
    __syncthreads();
    if (tg == 0) {
        smf[OFRD + (16 * wr + g) * 4 + wc]     = ds0;
        smf[OFRD + (16 * wr + g + 8) * 4 + wc] = ds1;
    }
    __syncthreads();
    if (t < TM)
        out_ds[b * N + n0 + t] = (smf[OFRD + t * 4] + smf[OFRD + t * 4 + 1]) +
                                 (smf[OFRD + t * 4 + 2] + smf[OFRD + t * 4 + 3]);
}

}  // namespace

extern "C" void kernel_launch(void* const* d_in, const int* in_sizes, int n_in,
                              void* d_out, int out_size) {
    const float* state = (const float*)d_in[0];   // [B, N]
    const float* val   = (const float*)d_in[1];   // [B, N, D]
    const float* Wq    = (const float*)d_in[2];   // [D, R]
    const float* Wk    = (const float*)d_in[3];   // [D, R]

    float* out_ds = (float*)d_out;                // [B, N]
    float* out_dv = out_ds + B * N;               // [B, N, D]

    constexpr int QK_SMEM = (D * R + 2 * 32 * D) * 4;   // 128KB
    cudaFuncSetAttribute(qk_kernel, cudaFuncAttributeMaxDynamicSharedMemorySize, QK_SMEM);
    cudaFuncSetAttribute(prop_kernel, cudaFuncAttributeMaxDynamicSharedMemorySize, SMEM_BYTES);

    qk_kernel<<<(B * N / 128) * 2, 256, QK_SMEM>>>(val, Wq, Wk);
    vt_kernel<<<dim3(N / 64, D / 64, B), 256>>>(val);
    prop_kernel<<<dim3(N / TM, B), THREADS, SMEM_BYTES>>>(state, out_ds, out_dv);
}